// round 14
// baseline (speedup 1.0000x reference)
#include <cuda_runtime.h>
#include <math.h>

#define BATCH 4
#define SEQ_M 1024
#define HDIM  1024
#define NHEAD 8
#define DHEAD 128
#define SEQ_L 1024
#define NEXP  8
#define FDIM  4096
#define NTOK  (BATCH*SEQ_M)
#define NBH   (BATCH*NHEAD)
#define LT    (SEQ_L+SEQ_M)
#define NSLOT (NTOK*2)

// ---------------- scratch (device globals) -------------------------------------
__device__ float g_q[(size_t)NBH*SEQ_M*DHEAD];
__device__ float g_k[(size_t)NBH*LT*DHEAD];
__device__ float g_v[(size_t)NBH*LT*DHEAD];
__device__ float g_ao[(size_t)NTOK*HDIM];
__device__ float g_t1[(size_t)NTOK*HDIM];
__device__ float g_h1[(size_t)NTOK*HDIM];
__device__ float g_hidden[(size_t)NSLOT*FDIM];
__device__ float g_y[(size_t)NSLOT*HDIM];
__device__ int   g_cnt[NEXP];
__device__ int   g_cur[NEXP];
__device__ int   g_off[NEXP];
__device__ int   g_slot_token[NSLOT];
__device__ float g_slot_w[NSLOT];
__device__ int   g_token_slot[NTOK*2];
__device__ int   g_top_e[NTOK*2];
__device__ float g_top_w[NTOK*2];

// ---------------- tf32 helpers -----------------------------------------------
__device__ __forceinline__ unsigned f2tf(float x)
{
    unsigned y;
    asm("cvt.rna.tf32.f32 %0, %1;" : "=r"(y) : "f"(x));
    return y;
}
__device__ __forceinline__ float4 tf4(float4 v)
{
    return make_float4(__uint_as_float(f2tf(v.x)), __uint_as_float(f2tf(v.y)),
                       __uint_as_float(f2tf(v.z)), __uint_as_float(f2tf(v.w)));
}

#define MMA_TF32(d0,d1,d2,d3,a0,a1,a2,a3,b0,b1)                             \
    asm volatile("mma.sync.aligned.m16n8k8.row.col.f32.tf32.tf32.f32 "      \
        "{%0,%1,%2,%3}, {%4,%5,%6,%7}, {%8,%9}, {%0,%1,%2,%3};"             \
        : "+f"(d0),"+f"(d1),"+f"(d2),"+f"(d3)                               \
        : "r"(a0),"r"(a1),"r"(a2),"r"(a3),"r"(b0),"r"(b1));

// ---------------- tf32 128x128x32 GEMM (deep kblock, phase-split prefetch) ------
#define G32_SMEM_BYTES 69632

#define G32_DECLS                                                            \
    const int tid = threadIdx.x, lane = tid & 31, warp = tid >> 5;           \
    const int wm = warp >> 1, wn = warp & 1;                                 \
    const int fg = lane >> 2, fc = lane & 3;                                 \
    const int alm = tid & 127, kslot = (tid >> 7) * 16;                      \
    const int blkr = tid >> 5, bln = lane * 4;                               \
    extern __shared__ float smp[];                                           \
    const float4 z4 = make_float4(0.f, 0.f, 0.f, 0.f);                       \
    (void)z4;

#define AS(buf,k,m) smp[(buf)*4352 + (k)*136 + (m)]
#define BS(buf,k,n) smp[8704 + (buf)*4352 + (k)*136 + (n)]

#define G32_STA(buf, kbase, P0, P1) {                                        \
    const float* _q0 = (const float*)&(P0);                                  \
    const float* _q1 = (const float*)&(P1);                                  \
    _Pragma("unroll")                                                        \
    for (int i = 0; i < 4; i++) {                                            \
        AS(buf, (kbase)+i,   alm) = __uint_as_float(f2tf(_q0[i]));           \
        AS(buf, (kbase)+4+i, alm) = __uint_as_float(f2tf(_q1[i]));           \
    } }

#define G32_COMP8(cur, k8) {                                                 \
    unsigned afr[2][4], bfr[8][2];                                           \
    _Pragma("unroll")                                                        \
    for (int mt = 0; mt < 2; mt++) {                                         \
        const int mr = wm*32 + mt*16 + fg;                                   \
        afr[mt][0] = __float_as_uint(AS(cur, (k8)+fc,   mr));                \
        afr[mt][1] = __float_as_uint(AS(cur, (k8)+fc,   mr+8));              \
        afr[mt][2] = __float_as_uint(AS(cur, (k8)+fc+4, mr));                \
        afr[mt][3] = __float_as_uint(AS(cur, (k8)+fc+4, mr+8));              \
    }                                                                        \
    _Pragma("unroll")                                                        \
    for (int nt = 0; nt < 8; nt++) {                                         \
        const int nc = wn*64 + nt*8 + fg;                                    \
        bfr[nt][0] = __float_as_uint(BS(cur, (k8)+fc,   nc));                \
        bfr[nt][1] = __float_as_uint(BS(cur, (k8)+fc+4, nc));                \
    }                                                                        \
    _Pragma("unroll")                                                        \
    for (int mt = 0; mt < 2; mt++)                                           \
    _Pragma("unroll")                                                        \
    for (int nt = 0; nt < 8; nt++)                                           \
        MMA_TF32(acc[mt][nt][0],acc[mt][nt][1],acc[mt][nt][2],acc[mt][nt][3],\
                 afr[mt][0],afr[mt][1],afr[mt][2],afr[mt][3],                \
                 bfr[nt][0],bfr[nt][1]); }

#define G32_PROLOGUE(LDB, AVALID) {                                          \
    float4 a0 = z4, a1 = z4;                                                 \
    if (AVALID) { a0 = *(const float4*)(aptr + kslot);                       \
                  a1 = *(const float4*)(aptr + kslot + 4); }                 \
    float4 b0 = *(const float4*)(bptr + (size_t)blkr * (LDB));               \
    float4 b1 = *(const float4*)(bptr + (size_t)(blkr + 8) * (LDB));         \
    G32_STA(0, kslot, a0, a1)                                                \
    *(float4*)&BS(0, blkr,   bln) = tf4(b0);                                 \
    *(float4*)&BS(0, blkr+8, bln) = tf4(b1);                                 \
    if (AVALID) { a0 = *(const float4*)(aptr + kslot + 8);                   \
                  a1 = *(const float4*)(aptr + kslot + 12); }                \
    b0 = *(const float4*)(bptr + (size_t)(blkr + 16) * (LDB));               \
    b1 = *(const float4*)(bptr + (size_t)(blkr + 24) * (LDB));               \
    G32_STA(0, kslot + 8, a0, a1)                                            \
    *(float4*)&BS(0, blkr+16, bln) = tf4(b0);                                \
    *(float4*)&BS(0, blkr+24, bln) = tf4(b1);                                \
    }                                                                        \
    __syncthreads();

#define G32_LOOP(NKB, LDB, AVALID)                                           \
    float acc[2][8][4] = {};                                                 \
    for (int kb = 0; kb < (NKB); kb++) {                                     \
        const int cur = kb & 1;                                              \
        const bool pf = (kb + 1 < (NKB));                                    \
        float4 a0 = z4, a1 = z4, b0 = z4, b1 = z4;                           \
        if (pf) {                                                            \
            if (AVALID) {                                                    \
                a0 = *(const float4*)(aptr + (kb+1)*32 + kslot);             \
                a1 = *(const float4*)(aptr + (kb+1)*32 + kslot + 4);         \
            }                                                                \
            b0 = *(const float4*)(bptr + (size_t)((kb+1)*32 + blkr)*(LDB));  \
            b1 = *(const float4*)(bptr + (size_t)((kb+1)*32 + blkr+8)*(LDB));\
        }                                                                    \
        G32_COMP8(cur, 0)                                                    \
        G32_COMP8(cur, 8)                                                    \
        if (pf) {                                                            \
            const int nxt = cur ^ 1;                                         \
            G32_STA(nxt, kslot, a0, a1)                                      \
            *(float4*)&BS(nxt, blkr,   bln) = tf4(b0);                       \
            *(float4*)&BS(nxt, blkr+8, bln) = tf4(b1);                       \
            if (AVALID) {                                                    \
                a0 = *(const float4*)(aptr + (kb+1)*32 + kslot + 8);         \
                a1 = *(const float4*)(aptr + (kb+1)*32 + kslot + 12);        \
            }                                                                \
            b0 = *(const float4*)(bptr + (size_t)((kb+1)*32 + blkr+16)*(LDB));\
            b1 = *(const float4*)(bptr + (size_t)((kb+1)*32 + blkr+24)*(LDB));\
        }                                                                    \
        G32_COMP8(cur, 16)                                                   \
        G32_COMP8(cur, 24)                                                   \
        if (pf) {                                                            \
            const int nxt = cur ^ 1;                                         \
            G32_STA(nxt, kslot + 8, a0, a1)                                  \
            *(float4*)&BS(nxt, blkr+16, bln) = tf4(b0);                      \
            *(float4*)&BS(nxt, blkr+24, bln) = tf4(b1);                      \
        }                                                                    \
        __syncthreads();                                                     \
    }

// ---------------- block reductions (256 threads / 8 warps) --------------------
__device__ __forceinline__ float blk_sum8(float v, float* sbuf)
{
    const int lane = threadIdx.x & 31, w = threadIdx.x >> 5;
#pragma unroll
    for (int o = 16; o; o >>= 1) v += __shfl_xor_sync(0xffffffffu, v, o);
    __syncthreads();
    if (lane == 0) sbuf[w] = v;
    __syncthreads();
    return sbuf[0]+sbuf[1]+sbuf[2]+sbuf[3]+sbuf[4]+sbuf[5]+sbuf[6]+sbuf[7];
}

// ---------------- init ----------------------------------------------------------
__global__ void k_init()
{
    int t = threadIdx.x;
    if (t < NEXP) { g_cnt[t] = 0; g_cur[t] = 0; }
}

// ---------------- fused QKV projections (one launch, tail-filled) -----------------
__global__ void __launch_bounds__(256) k_qkv(
    const float* __restrict__ h, const float* __restrict__ h_cache,
    const float* __restrict__ Wq, const float* __restrict__ Wk,
    const float* __restrict__ Wv)
{
    G32_DECLS
    const int bid = blockIdx.x;
    int job, mb, nb;
    if (bid < 256)      { job = 0; mb = bid >> 3;          nb = bid & 7; }
    else if (bid < 768) { job = 1; mb = (bid - 256) >> 3;  nb = bid & 7; }
    else                { job = 2; mb = (bid - 768) >> 3;  nb = bid & 7; }
    const int m0 = mb * 128, n0 = nb * 128;
    const float* W = (job == 0) ? Wq : (job == 1) ? Wk : Wv;

    const int arow = m0 + alm;
    const float* aptr;
    if (job == 0) {
        aptr = h + (size_t)arow * HDIM;
    } else {
        const int b = arow >> 11, t = arow & 2047;
        aptr = (t < SEQ_L) ? (h_cache + ((size_t)b * SEQ_L + t) * HDIM)
                           : (h + ((size_t)b * SEQ_M + (t - SEQ_L)) * HDIM);
    }
    const float* bptr = W + n0 + bln;

    G32_PROLOGUE(HDIM, true)
    G32_LOOP(HDIM/32, HDIM, true)

#pragma unroll
    for (int mt = 0; mt < 2; mt++) {
        const int r0 = m0 + wm*32 + mt*16 + fg;
        const int r1 = r0 + 8;
#pragma unroll
        for (int nt = 0; nt < 8; nt++) {
            const int col = n0 + wn*64 + nt*8 + fc*2;
            const int nh = col >> 7, d = col & 127;
            float *o0, *o1;
            if (job == 0) {
                int b = r0 >> 10, mm = r0 & 1023;
                o0 = g_q + (((size_t)(b*NHEAD + nh) * SEQ_M + mm) * DHEAD + d);
                b = r1 >> 10; mm = r1 & 1023;
                o1 = g_q + (((size_t)(b*NHEAD + nh) * SEQ_M + mm) * DHEAD + d);
            } else {
                float* base = (job == 1) ? g_k : g_v;
                int b = r0 >> 11, t = r0 & 2047;
                o0 = base + (((size_t)(b*NHEAD + nh) * LT + t) * DHEAD + d);
                b = r1 >> 11; t = r1 & 2047;
                o1 = base + (((size_t)(b*NHEAD + nh) * LT + t) * DHEAD + d);
            }
            *(float2*)o0 = make_float2(acc[mt][nt][0], acc[mt][nt][1]);
            *(float2*)o1 = make_float2(acc[mt][nt][2], acc[mt][nt][3]);
        }
    }
}

// ---------------- fused flash attention (no g_s) ------------------------------------
// Block: (i-block of 64 rows, bh). 256 threads (ty 0..15 x tx 0..15).
// smem floats: Qt[128][68] @0, Pt[64][68] @8704, work @13056 (Ks[16][128]+Ps[16][68] | Vs[128][68])
#define ATT_SMEM_BYTES (21760*4)

__global__ void __launch_bounds__(256) k_attn(const float* __restrict__ pos)
{
    extern __shared__ float sm[];
    float* Qt = sm;
    float* Pt = sm + 8704;
    float* Ks = sm + 13056;
    float* Ps = sm + 13056 + 2048;
    float* Vs = sm + 13056;

    const int bh = blockIdx.y;
    const int i0 = blockIdx.x * 64;
    const int tid = threadIdx.x, ty = tid >> 4, tx = tid & 15;
    const float* qbase = g_q + (size_t)bh * SEQ_M * DHEAD;
    const float* kbase = g_k + (size_t)bh * LT * DHEAD;
    const float* vbase = g_v + (size_t)bh * LT * DHEAD;

    // load Q tile transposed: Qt[d][i]
    {
        const int qi = tid & 63;
        const int dg = (tid >> 6) * 32;
        const float* qrow = qbase + (size_t)(i0 + qi) * DHEAD + dg;
#pragma unroll
        for (int p = 0; p < 8; p++) {
            float4 v = *(const float4*)(qrow + p*4);
            Qt[(dg + p*4 + 0)*68 + qi] = v.x;
            Qt[(dg + p*4 + 1)*68 + qi] = v.y;
            Qt[(dg + p*4 + 2)*68 + qi] = v.z;
            Qt[(dg + p*4 + 3)*68 + qi] = v.w;
        }
    }

    const int il0 = ty * 4;
    float m_prev[4] = {-1e30f, -1e30f, -1e30f, -1e30f};
    float l_run[4] = {0.f, 0.f, 0.f, 0.f};
    float oacc[4][8] = {};

    const int kr = tid >> 1, kk8 = (tid & 1) * 8;
    const int pk = tid >> 4, pj = (tid & 15) * 4;
    const float scale = 1.0f / 32.0f;

    for (int jc = 0; jc < 16; jc++) {
        const int j0 = jc * 64;
        float sacc[4][4] = {};
        for (int dc = 0; dc < DHEAD; dc += 16) {
            __syncthreads();   // guards Ks/Ps (and Vs-region) reuse
            float4 k0 = *(const float4*)(kbase + (size_t)(i0+j0+kr)*DHEAD + dc + kk8);
            float4 k1 = *(const float4*)(kbase + (size_t)(i0+j0+kr)*DHEAD + dc + kk8 + 4);
            Ks[(kk8+0)*128+kr]=k0.x; Ks[(kk8+1)*128+kr]=k0.y;
            Ks[(kk8+2)*128+kr]=k0.z; Ks[(kk8+3)*128+kr]=k0.w;
            Ks[(kk8+4)*128+kr]=k1.x; Ks[(kk8+5)*128+kr]=k1.y;
            Ks[(kk8+6)*128+kr]=k1.z; Ks[(kk8+7)*128+kr]=k1.w;
            *(float4*)&Ps[pk*68 + pj] =
                *(const float4*)(pos + (size_t)(dc + pk) * SEQ_L + j0 + pj);
            __syncthreads();
            const int base = (ty + tx) * 4;
#pragma unroll
            for (int kk = 0; kk < 16; kk++) {
                float4 q4 = *(const float4*)&Qt[(dc+kk)*68 + il0];
                float4 p4 = *(const float4*)&Ps[kk*68 + tx*4];
                float4 ka = *(const float4*)&Ks[kk*128 + base];
                float4 kb = *(const float4*)&Ks[kk*128 + base + 4];
                float qr[4] = {q4.x,q4.y,q4.z,q4.w};
                float pr[4] = {p4.x,p4.y,p4.z,p4.w};
                float kv[8] = {ka.x,ka.y,ka.z,ka.w,kb.x,kb.y,kb.z,kb.w};
#pragma unroll
                for (int i = 0; i < 4; i++)
#pragma unroll
                    for (int j = 0; j < 4; j++)
                        sacc[i][j] = fmaf(qr[i], kv[i+j] + pr[j], sacc[i][j]);
            }
        }

        // online softmax update (per-row, replicated across tx group)
        float pblk[4][4];
#pragma unroll
        for (int u = 0; u < 4; u++) {
            float s0 = sacc[u][0]*scale, s1 = sacc[u][1]*scale;
            float s2 = sacc[u][2]*scale, s3 = sacc[u][3]*scale;
            float mx = fmaxf(fmaxf(s0, s1), fmaxf(s2, s3));
#pragma unroll
            for (int o = 8; o; o >>= 1)
                mx = fmaxf(mx, __shfl_xor_sync(0xffffffffu, mx, o));
            const float mnew = fmaxf(m_prev[u], mx);
            const float fac = __expf(m_prev[u] - mnew);
            float p0 = __expf(s0 - mnew), p1 = __expf(s1 - mnew);
            float p2 = __expf(s2 - mnew), p3 = __expf(s3 - mnew);
            float rs = p0 + p1 + p2 + p3;
#pragma unroll
            for (int o = 8; o; o >>= 1)
                rs += __shfl_xor_sync(0xffffffffu, rs, o);
            l_run[u] = l_run[u] * fac + rs;
            m_prev[u] = mnew;
#pragma unroll
            for (int d = 0; d < 8; d++) oacc[u][d] *= fac;
            pblk[u][0] = p0; pblk[u][1] = p1; pblk[u][2] = p2; pblk[u][3] = p3;
        }
        __syncthreads();   // QK compute fully done -> safe to overwrite Ks/Ps (Vs) & write Pt
#pragma unroll
        for (int v = 0; v < 4; v++)
            *(float4*)&Pt[(tx*4+v)*68 + il0] =
                make_float4(pblk[0][v], pblk[1][v], pblk[2][v], pblk[3][v]);

        // PV in two 64-col halves
#pragma unroll
        for (int hf = 0; hf < 2; hf++) {
            if (hf) __syncthreads();   // previous half's reads done
            {
                const int r = tid >> 1, c = (tid & 1) * 32;
                const float* vrow = vbase + (size_t)(i0 + j0 + r) * DHEAD + hf*64 + c;
#pragma unroll
                for (int p = 0; p < 8; p++)
                    *(float4*)&Vs[r*68 + c + p*4] = *(const float4*)(vrow + p*4);
            }
            __syncthreads();
            const int d4 = tx * 4;
            float4 vw0 = *(const float4*)&Vs[(il0+0)*68 + d4];
            float4 vw1 = *(const float4*)&Vs[(il0+1)*68 + d4];
            float4 vw2 = *(const float4*)&Vs[(il0+2)*68 + d4];
            float4 vw3 = *(const float4*)&Vs[(il0+3)*68 + d4];
            const int ob = hf * 4;
#pragma unroll 8
            for (int jl = 0; jl < 64; jl++) {
                float4 p4 = *(const float4*)&Pt[jl*68 + il0];
                oacc[0][ob+0] = fmaf(p4.x, vw0.x, oacc[0][ob+0]);
                oacc[0][ob+1] = fmaf(p4.x, vw0.y, oacc[0][ob+1]);
                oacc[0][ob+2] = fmaf(p4.x, vw0.z, oacc[0][ob+2]);
                oacc[0][ob+3] = fmaf(p4.x, vw0.w, oacc[0][ob+3]);
                oacc[1][ob+0] = fmaf(p4.y, vw1.x, oacc[1][ob+0]);
                oacc[1][ob+1] = fmaf(p4.y, vw1.y, oacc[1][ob+1]);
                oacc[1][ob+2] = fmaf(p4.y, vw1.z, oacc[1][ob+2]);
                oacc[1][ob+3] = fmaf(p4.y, vw1.w, oacc[1][ob+3]);
                oacc[2][ob+0] = fmaf(p4.z, vw2.x, oacc[2][ob+0]);
                oacc[2][ob+1] = fmaf(p4.z, vw2.y, oacc[2][ob+1]);
                oacc[2][ob+2] = fmaf(p4.z, vw2.z, oacc[2][ob+2]);
                oacc[2][ob+3] = fmaf(p4.z, vw2.w, oacc[2][ob+3]);
                oacc[3][ob+0] = fmaf(p4.w, vw3.x, oacc[3][ob+0]);
                oacc[3][ob+1] = fmaf(p4.w, vw3.y, oacc[3][ob+1]);
                oacc[3][ob+2] = fmaf(p4.w, vw3.z, oacc[3][ob+2]);
                oacc[3][ob+3] = fmaf(p4.w, vw3.w, oacc[3][ob+3]);
                vw0 = vw1; vw1 = vw2; vw2 = vw3;
                vw3 = *(const float4*)&Vs[(il0 + jl + 4)*68 + d4];
            }
        }
    }

    const int b = bh >> 3, nh = bh & 7;
#pragma unroll
    for (int u = 0; u < 4; u++) {
        const float inv = 1.0f / l_run[u];
        float* o = g_ao + ((size_t)(b*SEQ_M + i0 + il0 + u)) * HDIM + nh * DHEAD;
        *(float4*)(o + tx*4) = make_float4(
            oacc[u][0]*inv, oacc[u][1]*inv, oacc[u][2]*inv, oacc[u][3]*inv);
        *(float4*)(o + 64 + tx*4) = make_float4(
            oacc[u][4]*inv, oacc[u][5]*inv, oacc[u][6]*inv, oacc[u][7]*inv);
    }
}

// ---------------- Wo projection + residual (tf32 tensor, deep-k) ----------------------
__global__ void __launch_bounds__(256) k_wo(const float* __restrict__ Wo,
                                            const float* __restrict__ h)
{
    G32_DECLS
    const int m0 = blockIdx.y * 128, n0 = blockIdx.x * 128;

    const float* aptr = g_ao + (size_t)(m0 + alm) * HDIM;
    const float* bptr = Wo + n0 + bln;

    G32_PROLOGUE(HDIM, true)
    G32_LOOP(HDIM/32, HDIM, true)

#pragma unroll
    for (int mt = 0; mt < 2; mt++) {
        const int r0 = m0 + wm*32 + mt*16 + fg;
        const int r1 = r0 + 8;
#pragma unroll
        for (int nt = 0; nt < 8; nt++) {
            const int col = n0 + wn*64 + nt*8 + fc*2;
            float2 h0 = *(const float2*)(h + (size_t)r0 * HDIM + col);
            float2 h1 = *(const float2*)(h + (size_t)r1 * HDIM + col);
            *(float2*)(g_t1 + (size_t)r0 * HDIM + col) =
                make_float2(acc[mt][nt][0] + h0.x, acc[mt][nt][1] + h0.y);
            *(float2*)(g_t1 + (size_t)r1 * HDIM + col) =
                make_float2(acc[mt][nt][2] + h1.x, acc[mt][nt][3] + h1.y);
        }
    }
}

// ---------------- fused LN1 + gate ------------------------------------------------------
__global__ void __launch_bounds__(256) k_ln1gate(
    const float* __restrict__ g, const float* __restrict__ b,
    const float* __restrict__ gw, const float* __restrict__ gb)
{
    __shared__ float sbuf[8];
    __shared__ float xs[HDIM];
    __shared__ float lg[NEXP];
    const int row = blockIdx.x;
    const int c0 = threadIdx.x * 4;
    float4 xv = *(const float4*)(g_t1 + (size_t)row * HDIM + c0);
    float s  = xv.x + xv.y + xv.z + xv.w;
    float s2 = xv.x*xv.x + xv.y*xv.y + xv.z*xv.z + xv.w*xv.w;
    s  = blk_sum8(s,  sbuf);
    s2 = blk_sum8(s2, sbuf);
    const float mu = s * (1.0f / HDIM);
    const float var = s2 * (1.0f / HDIM) - mu * mu;
    const float inv = rsqrtf(var + 1e-5f);
    float4 gv = *(const float4*)(g + c0);
    float4 bv = *(const float4*)(b + c0);
    float4 r = make_float4(
        (xv.x - mu) * inv * gv.x + bv.x,
        (xv.y - mu) * inv * gv.y + bv.y,
        (xv.z - mu) * inv * gv.z + bv.z,
        (xv.w - mu) * inv * gv.w + bv.w);
    *(float4*)(g_h1 + (size_t)row * HDIM + c0) = r;
    *(float4*)&xs[c0] = r;
    __syncthreads();

    const int w = threadIdx.x >> 5, lane = threadIdx.x & 31;
    float sg = 0.0f;
    for (int hh = lane; hh < HDIM; hh += 32)
        sg = fmaf(xs[hh], gw[hh * NEXP + w], sg);
#pragma unroll
    for (int o = 16; o; o >>= 1) sg += __shfl_xor_sync(0xffffffffu, sg, o);
    if (lane == 0) lg[w] = sg + gb[w];
    __syncthreads();
    if (threadIdx.x == 0) {
        int i0 = 0;
        for (int e = 1; e < NEXP; e++) if (lg[e] > lg[i0]) i0 = e;
        int i1 = -1;
        for (int e = 0; e < NEXP; e++) {
            if (e == i0) continue;
            if (i1 < 0 || lg[e] > lg[i1]) i1 = e;
        }
        const float e1 = __expf(lg[i1] - lg[i0]);
        const float den = 1.0f / (1.0f + e1);
        g_top_e[2*row]   = i0; g_top_e[2*row+1] = i1;
        g_top_w[2*row]   = den;
        g_top_w[2*row+1] = e1 * den;
        atomicAdd(&g_cnt[i0], 1);
        atomicAdd(&g_cnt[i1], 1);
    }
}

__global__ void k_scan()
{
    int s = 0;
    for (int e = 0; e < NEXP; e++) { g_off[e] = s; s += g_cnt[e]; }
}

__global__ void __launch_bounds__(256) k_scatter()
{
    const int t = blockIdx.x * 256 + threadIdx.x;
    if (t >= NTOK) return;
#pragma unroll
    for (int k = 0; k < 2; k++) {
        const int e = g_top_e[2*t + k];
        const int p = atomicAdd(&g_cur[e], 1);
        const int pos = g_off[e] + p;
        g_slot_token[pos] = t;
        g_slot_w[pos] = g_top_w[2*t + k];
        g_token_slot[2*t + k] = pos;
    }
}

// ---------------- MoE GEMM1 (tf32 tensor, deep-k) ----------------------------------------
__global__ void __launch_bounds__(256) k_moe1(const float* __restrict__ w1,
                                              const float* __restrict__ b1)
{
    const int e = blockIdx.z;
    const int cnt = g_cnt[e];
    const int r0b = blockIdx.y * 128;
    if (r0b >= cnt) return;
    const int off = g_off[e];

    __shared__ int toks[128];
    G32_DECLS
    const int n0 = blockIdx.x * 128;

    if (tid < 128) {
        const int r = r0b + tid;
        toks[tid] = (r < cnt) ? g_slot_token[off + r] : -1;
    }
    __syncthreads();
    const int tok = toks[alm];
    const bool aval = (tok >= 0);
    const float* aptr = g_h1 + (size_t)(aval ? tok : 0) * HDIM;
    const float* bptr = w1 + (size_t)e * HDIM * FDIM + n0 + bln;

    G32_PROLOGUE(FDIM, aval)
    G32_LOOP(HDIM/32, FDIM, aval)

#pragma unroll
    for (int mt = 0; mt < 2; mt++) {
        const int r0 = r0b + wm*32 + mt*16 + fg;
        const int r1 = r0 + 8;
#pragma unroll
        for (int nt = 0; nt < 8; nt++) {
            const int col = n0 + wn*64 + nt*8 + fc*2;
            float2 bb = *(const float2*)(b1 + (size_t)e * FDIM + col);
            if (r0 < cnt)
                *(float2*)(g_hidden + (size_t)(off + r0) * FDIM + col) =
                    make_float2(fmaxf(acc[mt][nt][0] + bb.x, 0.f),
                                fmaxf(acc[mt][nt][1] + bb.y, 0.f));
            if (r1 < cnt)
                *(float2*)(g_hidden + (size_t)(off + r1) * FDIM + col) =
                    make_float2(fmaxf(acc[mt][nt][2] + bb.x, 0.f),
                                fmaxf(acc[mt][nt][3] + bb.y, 0.f));
        }
    }
}

// ---------------- MoE GEMM2 (tf32 tensor, deep-k) ------------------------------------------
__global__ void __launch_bounds__(256) k_moe2(const float* __restrict__ w2,
                                              const float* __restrict__ b2)
{
    const int e = blockIdx.z;
    const int cnt = g_cnt[e];
    const int r0b = blockIdx.y * 128;
    if (r0b >= cnt) return;
    const int off = g_off[e];

    G32_DECLS
    const int n0 = blockIdx.x * 128;

    const int r = r0b + alm;
    const bool aval = (r < cnt);
    const float* aptr = g_hidden + (size_t)(off + (aval ? r : 0)) * FDIM;
    const float* bptr = w2 + (size_t)e * FDIM * HDIM + n0 + bln;

    G32_PROLOGUE(HDIM, aval)
    G32_LOOP(FDIM/32, HDIM, aval)

#pragma unroll
    for (int mt = 0; mt < 2; mt++) {
        const int r0 = r0b + wm*32 + mt*16 + fg;
        const int r1 = r0 + 8;
#pragma unroll
        for (int nt = 0; nt < 8; nt++) {
            const int col = n0 + wn*64 + nt*8 + fc*2;
            float2 bb = *(const float2*)(b2 + (size_t)e * HDIM + col);
            if (r0 < cnt)
                *(float2*)(g_y + (size_t)(off + r0) * HDIM + col) =
                    make_float2(acc[mt][nt][0] + bb.x, acc[mt][nt][1] + bb.y);
            if (r1 < cnt)
                *(float2*)(g_y + (size_t)(off + r1) * HDIM + col) =
                    make_float2(acc[mt][nt][2] + bb.x, acc[mt][nt][3] + bb.y);
        }
    }
}

// ---------------- combine + LN2 -----------------------------------------------------------
__global__ void __launch_bounds__(256) k_combine(const float* __restrict__ mom_in,
                                                 const float* __restrict__ g,
                                                 const float* __restrict__ b,
                                                 float* __restrict__ out)
{
    __shared__ float sbuf[8];
    const int t = blockIdx.x;
    const int s0 = g_token_slot[2*t], s1 = g_token_slot[2*t + 1];
    const float w0 = g_slot_w[s0], w1 = g_slot_w[s1];
    const int c0 = threadIdx.x * 4;

    float4 h1v = *(const float4*)(g_h1 + (size_t)t * HDIM + c0);
    float4 mv  = *(const float4*)(mom_in + (size_t)t * HDIM + c0);
    float4 y0  = *(const float4*)(g_y + (size_t)s0 * HDIM + c0);
    float4 y1  = *(const float4*)(g_y + (size_t)s1 * HDIM + c0);

    float momn[4], x[4];
    momn[0] = 0.7f*mv.x + w0*y0.x + w1*y1.x;
    momn[1] = 0.7f*mv.y + w0*y0.y + w1*y1.y;
    momn[2] = 0.7f*mv.z + w0*y0.z + w1*y1.z;
    momn[3] = 0.7f*mv.w + w0*y0.w + w1*y1.w;
    x[0] = h1v.x - momn[0]; x[1] = h1v.y - momn[1];
    x[2] = h1v.z - momn[2]; x[3] = h1v.w - momn[3];

    float s  = x[0] + x[1] + x[2] + x[3];
    float s2 = x[0]*x[0] + x[1]*x[1] + x[2]*x[2] + x[3]*x[3];
    s  = blk_sum8(s,  sbuf);
    s2 = blk_sum8(s2, sbuf);
    const float mu = s * (1.0f / HDIM);
    const float var = s2 * (1.0f / HDIM) - mu * mu;
    const float inv = rsqrtf(var + 1e-5f);
    float4 gv = *(const float4*)(g + c0);
    float4 bv = *(const float4*)(b + c0);

    *(float4*)(out + (size_t)t * HDIM + c0) = make_float4(
        (x[0] - mu) * inv * gv.x + bv.x,
        (x[1] - mu) * inv * gv.y + bv.y,
        (x[2] - mu) * inv * gv.z + bv.z,
        (x[3] - mu) * inv * gv.w + bv.w);
    *(float4*)(out + (size_t)NTOK * HDIM + (size_t)t * HDIM + c0) =
        make_float4(momn[0], momn[1], momn[2], momn[3]);
}

// ---------------- launch ---------------------------------------------------------------------
extern "C" void kernel_launch(void* const* d_in, const int* in_sizes, int n_in,
                              void* d_out, int out_size)
{
    const float* h       = (const float*)d_in[0];
    const float* h_cache = (const float*)d_in[1];
    const float* pos     = (const float*)d_in[2];
    const float* mom     = (const float*)d_in[3];
    const float* Wq      = (const float*)d_in[4];
    const float* Wk      = (const float*)d_in[5];
    const float* Wv      = (const float*)d_in[6];
    const float* Wo      = (const float*)d_in[7];
    const float* gate_w  = (const float*)d_in[8];
    const float* gate_b  = (const float*)d_in[9];
    const float* w1      = (const float*)d_in[10];
    const float* b1      = (const float*)d_in[11];
    const float* w2      = (const float*)d_in[12];
    const float* b2      = (const float*)d_in[13];
    const float* ln1g    = (const float*)d_in[14];
    const float* ln1b    = (const float*)d_in[15];
    const float* ln2g    = (const float*)d_in[16];
    const float* ln2b    = (const float*)d_in[17];
    float* out = (float*)d_out;

    cudaFuncSetAttribute(k_qkv,  cudaFuncAttributeMaxDynamicSharedMemorySize, G32_SMEM_BYTES);
    cudaFuncSetAttribute(k_attn, cudaFuncAttributeMaxDynamicSharedMemorySize, ATT_SMEM_BYTES);
    cudaFuncSetAttribute(k_wo,   cudaFuncAttributeMaxDynamicSharedMemorySize, G32_SMEM_BYTES);
    cudaFuncSetAttribute(k_moe1, cudaFuncAttributeMaxDynamicSharedMemorySize, G32_SMEM_BYTES);
    cudaFuncSetAttribute(k_moe2, cudaFuncAttributeMaxDynamicSharedMemorySize, G32_SMEM_BYTES);

    k_init<<<1, 32>>>();
    k_qkv<<<1280, 256, G32_SMEM_BYTES>>>(h, h_cache, Wq, Wk, Wv);
    k_attn<<<dim3(SEQ_M/64, NBH), 256, ATT_SMEM_BYTES>>>(pos);
    k_wo<<<dim3(HDIM/128, NTOK/128), 256, G32_SMEM_BYTES>>>(Wo, h);
    k_ln1gate<<<NTOK, 256>>>(ln1g, ln1b, gate_w, gate_b);
    k_scan<<<1, 1>>>();
    k_scatter<<<NTOK/256, 256>>>();
    k_moe1<<<dim3(FDIM/128, NSLOT/128, NEXP), 256, G32_SMEM_BYTES>>>(w1, b1);
    k_moe2<<<dim3(HDIM/128, NSLOT/128, NEXP), 256, G32_SMEM_BYTES>>>(w2, b2);
    k_combine<<<NTOK, 256>>>(mom, ln2g, ln2b, out);
}

// round 15
// speedup vs baseline: 1.0984x; 1.0984x over previous
#include <cuda_runtime.h>
#include <math.h>

#define BATCH 4
#define SEQ_M 1024
#define HDIM  1024
#define NHEAD 8
#define DHEAD 128
#define SEQ_L 1024
#define NEXP  8
#define FDIM  4096
#define NTOK  (BATCH*SEQ_M)
#define NBH   (BATCH*NHEAD)
#define LT    (SEQ_L+SEQ_M)
#define NSLOT (NTOK*2)

// ---------------- scratch (device globals) -------------------------------------
__device__ float g_q[(size_t)NBH*SEQ_M*DHEAD];
__device__ float g_k[(size_t)NBH*LT*DHEAD];
__device__ float g_v[(size_t)NBH*LT*DHEAD];
__device__ float g_s[(size_t)NBH*SEQ_M*SEQ_L];
__device__ float g_ao[(size_t)NTOK*HDIM];
__device__ float g_t1[(size_t)NTOK*HDIM];
__device__ float g_h1[(size_t)NTOK*HDIM];
__device__ float g_hidden[(size_t)NSLOT*FDIM];
__device__ float g_y[(size_t)NSLOT*HDIM];
__device__ int   g_cnt[NEXP];
__device__ int   g_cur[NEXP];
__device__ int   g_off[NEXP];
__device__ int   g_slot_token[NSLOT];
__device__ float g_slot_w[NSLOT];
__device__ int   g_token_slot[NTOK*2];
__device__ int   g_top_e[NTOK*2];
__device__ float g_top_w[NTOK*2];

// ---------------- tf32 helpers -----------------------------------------------
__device__ __forceinline__ unsigned f2tf(float x)
{
    unsigned y;
    asm("cvt.rna.tf32.f32 %0, %1;" : "=r"(y) : "f"(x));
    return y;
}
__device__ __forceinline__ float4 tf4(float4 v)
{
    return make_float4(__uint_as_float(f2tf(v.x)), __uint_as_float(f2tf(v.y)),
                       __uint_as_float(f2tf(v.z)), __uint_as_float(f2tf(v.w)));
}

#define MMA_TF32(d0,d1,d2,d3,a0,a1,a2,a3,b0,b1)                             \
    asm volatile("mma.sync.aligned.m16n8k8.row.col.f32.tf32.tf32.f32 "      \
        "{%0,%1,%2,%3}, {%4,%5,%6,%7}, {%8,%9}, {%0,%1,%2,%3};"             \
        : "+f"(d0),"+f"(d1),"+f"(d2),"+f"(d3)                               \
        : "r"(a0),"r"(a1),"r"(a2),"r"(a3),"r"(b0),"r"(b1));

// ---------------- tf32 128x128x32 GEMM (deep kblock, phase-split prefetch) ------
#define G32_SMEM_BYTES 69632

#define G32_DECLS                                                            \
    const int tid = threadIdx.x, lane = tid & 31, warp = tid >> 5;           \
    const int wm = warp >> 1, wn = warp & 1;                                 \
    const int fg = lane >> 2, fc = lane & 3;                                 \
    const int alm = tid & 127, kslot = (tid >> 7) * 16;                      \
    const int blkr = tid >> 5, bln = lane * 4;                               \
    extern __shared__ float smp[];                                           \
    const float4 z4 = make_float4(0.f, 0.f, 0.f, 0.f);                       \
    (void)z4;

#define AS(buf,k,m) smp[(buf)*4352 + (k)*136 + (m)]
#define BS(buf,k,n) smp[8704 + (buf)*4352 + (k)*136 + (n)]

#define G32_STA(buf, kbase, P0, P1) {                                        \
    const float* _q0 = (const float*)&(P0);                                  \
    const float* _q1 = (const float*)&(P1);                                  \
    _Pragma("unroll")                                                        \
    for (int i = 0; i < 4; i++) {                                            \
        AS(buf, (kbase)+i,   alm) = __uint_as_float(f2tf(_q0[i]));           \
        AS(buf, (kbase)+4+i, alm) = __uint_as_float(f2tf(_q1[i]));           \
    } }

#define G32_COMP8(cur, k8) {                                                 \
    unsigned afr[2][4], bfr[8][2];                                           \
    _Pragma("unroll")                                                        \
    for (int mt = 0; mt < 2; mt++) {                                         \
        const int mr = wm*32 + mt*16 + fg;                                   \
        afr[mt][0] = __float_as_uint(AS(cur, (k8)+fc,   mr));                \
        afr[mt][1] = __float_as_uint(AS(cur, (k8)+fc,   mr+8));              \
        afr[mt][2] = __float_as_uint(AS(cur, (k8)+fc+4, mr));                \
        afr[mt][3] = __float_as_uint(AS(cur, (k8)+fc+4, mr+8));              \
    }                                                                        \
    _Pragma("unroll")                                                        \
    for (int nt = 0; nt < 8; nt++) {                                         \
        const int nc = wn*64 + nt*8 + fg;                                    \
        bfr[nt][0] = __float_as_uint(BS(cur, (k8)+fc,   nc));                \
        bfr[nt][1] = __float_as_uint(BS(cur, (k8)+fc+4, nc));                \
    }                                                                        \
    _Pragma("unroll")                                                        \
    for (int mt = 0; mt < 2; mt++)                                           \
    _Pragma("unroll")                                                        \
    for (int nt = 0; nt < 8; nt++)                                           \
        MMA_TF32(acc[mt][nt][0],acc[mt][nt][1],acc[mt][nt][2],acc[mt][nt][3],\
                 afr[mt][0],afr[mt][1],afr[mt][2],afr[mt][3],                \
                 bfr[nt][0],bfr[nt][1]); }

#define G32_PROLOGUE(LDB, AVALID) {                                          \
    float4 a0 = z4, a1 = z4;                                                 \
    if (AVALID) { a0 = *(const float4*)(aptr + kslot);                       \
                  a1 = *(const float4*)(aptr + kslot + 4); }                 \
    float4 b0 = *(const float4*)(bptr + (size_t)blkr * (LDB));               \
    float4 b1 = *(const float4*)(bptr + (size_t)(blkr + 8) * (LDB));         \
    G32_STA(0, kslot, a0, a1)                                                \
    *(float4*)&BS(0, blkr,   bln) = tf4(b0);                                 \
    *(float4*)&BS(0, blkr+8, bln) = tf4(b1);                                 \
    if (AVALID) { a0 = *(const float4*)(aptr + kslot + 8);                   \
                  a1 = *(const float4*)(aptr + kslot + 12); }                \
    b0 = *(const float4*)(bptr + (size_t)(blkr + 16) * (LDB));               \
    b1 = *(const float4*)(bptr + (size_t)(blkr + 24) * (LDB));               \
    G32_STA(0, kslot + 8, a0, a1)                                            \
    *(float4*)&BS(0, blkr+16, bln) = tf4(b0);                                \
    *(float4*)&BS(0, blkr+24, bln) = tf4(b1);                                \
    }                                                                        \
    __syncthreads();

#define G32_LOOP(NKB, LDB, AVALID)                                           \
    float acc[2][8][4] = {};                                                 \
    for (int kb = 0; kb < (NKB); kb++) {                                     \
        const int cur = kb & 1;                                              \
        const bool pf = (kb + 1 < (NKB));                                    \
        float4 a0 = z4, a1 = z4, b0 = z4, b1 = z4;                           \
        if (pf) {                                                            \
            if (AVALID) {                                                    \
                a0 = *(const float4*)(aptr + (kb+1)*32 + kslot);             \
                a1 = *(const float4*)(aptr + (kb+1)*32 + kslot + 4);         \
            }                                                                \
            b0 = *(const float4*)(bptr + (size_t)((kb+1)*32 + blkr)*(LDB));  \
            b1 = *(const float4*)(bptr + (size_t)((kb+1)*32 + blkr+8)*(LDB));\
        }                                                                    \
        G32_COMP8(cur, 0)                                                    \
        G32_COMP8(cur, 8)                                                    \
        if (pf) {                                                            \
            const int nxt = cur ^ 1;                                         \
            G32_STA(nxt, kslot, a0, a1)                                      \
            *(float4*)&BS(nxt, blkr,   bln) = tf4(b0);                       \
            *(float4*)&BS(nxt, blkr+8, bln) = tf4(b1);                       \
            if (AVALID) {                                                    \
                a0 = *(const float4*)(aptr + (kb+1)*32 + kslot + 8);         \
                a1 = *(const float4*)(aptr + (kb+1)*32 + kslot + 12);        \
            }                                                                \
            b0 = *(const float4*)(bptr + (size_t)((kb+1)*32 + blkr+16)*(LDB));\
            b1 = *(const float4*)(bptr + (size_t)((kb+1)*32 + blkr+24)*(LDB));\
        }                                                                    \
        G32_COMP8(cur, 16)                                                   \
        G32_COMP8(cur, 24)                                                   \
        if (pf) {                                                            \
            const int nxt = cur ^ 1;                                         \
            G32_STA(nxt, kslot + 8, a0, a1)                                  \
            *(float4*)&BS(nxt, blkr+16, bln) = tf4(b0);                      \
            *(float4*)&BS(nxt, blkr+24, bln) = tf4(b1);                      \
        }                                                                    \
        __syncthreads();                                                     \
    }

// ---------------- block reductions (256 threads / 8 warps) --------------------
__device__ __forceinline__ float blk_sum8(float v, float* sbuf)
{
    const int lane = threadIdx.x & 31, w = threadIdx.x >> 5;
#pragma unroll
    for (int o = 16; o; o >>= 1) v += __shfl_xor_sync(0xffffffffu, v, o);
    __syncthreads();
    if (lane == 0) sbuf[w] = v;
    __syncthreads();
    return sbuf[0]+sbuf[1]+sbuf[2]+sbuf[3]+sbuf[4]+sbuf[5]+sbuf[6]+sbuf[7];
}

// ---------------- init ----------------------------------------------------------
__global__ void k_init()
{
    int t = threadIdx.x;
    if (t < NEXP) { g_cnt[t] = 0; g_cur[t] = 0; }
}

// ---------------- fused QKV projections (one launch, tail-filled) -----------------
__global__ void __launch_bounds__(256) k_qkv(
    const float* __restrict__ h, const float* __restrict__ h_cache,
    const float* __restrict__ Wq, const float* __restrict__ Wk,
    const float* __restrict__ Wv)
{
    G32_DECLS
    const int bid = blockIdx.x;
    int job, mb, nb;
    if (bid < 256)      { job = 0; mb = bid >> 3;          nb = bid & 7; }
    else if (bid < 768) { job = 1; mb = (bid - 256) >> 3;  nb = bid & 7; }
    else                { job = 2; mb = (bid - 768) >> 3;  nb = bid & 7; }
    const int m0 = mb * 128, n0 = nb * 128;
    const float* W = (job == 0) ? Wq : (job == 1) ? Wk : Wv;

    const int arow = m0 + alm;
    const float* aptr;
    if (job == 0) {
        aptr = h + (size_t)arow * HDIM;
    } else {
        const int b = arow >> 11, t = arow & 2047;
        aptr = (t < SEQ_L) ? (h_cache + ((size_t)b * SEQ_L + t) * HDIM)
                           : (h + ((size_t)b * SEQ_M + (t - SEQ_L)) * HDIM);
    }
    const float* bptr = W + n0 + bln;

    G32_PROLOGUE(HDIM, true)
    G32_LOOP(HDIM/32, HDIM, true)

#pragma unroll
    for (int mt = 0; mt < 2; mt++) {
        const int r0 = m0 + wm*32 + mt*16 + fg;
        const int r1 = r0 + 8;
#pragma unroll
        for (int nt = 0; nt < 8; nt++) {
            const int col = n0 + wn*64 + nt*8 + fc*2;
            const int nh = col >> 7, d = col & 127;
            float *o0, *o1;
            if (job == 0) {
                int b = r0 >> 10, mm = r0 & 1023;
                o0 = g_q + (((size_t)(b*NHEAD + nh) * SEQ_M + mm) * DHEAD + d);
                b = r1 >> 10; mm = r1 & 1023;
                o1 = g_q + (((size_t)(b*NHEAD + nh) * SEQ_M + mm) * DHEAD + d);
            } else {
                float* base = (job == 1) ? g_k : g_v;
                int b = r0 >> 11, t = r0 & 2047;
                o0 = base + (((size_t)(b*NHEAD + nh) * LT + t) * DHEAD + d);
                b = r1 >> 11; t = r1 & 2047;
                o1 = base + (((size_t)(b*NHEAD + nh) * LT + t) * DHEAD + d);
            }
            *(float2*)o0 = make_float2(acc[mt][nt][0], acc[mt][nt][1]);
            *(float2*)o1 = make_float2(acc[mt][nt][2], acc[mt][nt][3]);
        }
    }
}

// ---------------- banded scores v2 (proven R11) -------------------------------------
__global__ void __launch_bounds__(256) k_scores(const float* __restrict__ pos)
{
    __shared__ float Qs[16][128];
    __shared__ float Ks[16][192];
    __shared__ float Ps[16][64];
    const int bh = blockIdx.z;
    const int i0 = blockIdx.y * 128, j0 = blockIdx.x * 64;
    const int tid = threadIdx.x, ty = tid >> 4, tx = tid & 15;

    const float* qbase = g_q + (size_t)bh * SEQ_M * DHEAD;
    const float* kbase = g_k + (size_t)bh * LT * DHEAD;

    const int qi = tid >> 1, qk = (tid & 1) * 8;
    const int pk = tid >> 4, pj = (tid & 15) * 4;
    const int kr = tid >> 1, kk8 = (tid & 1) * 8;

    float acc[8][4] = {};
    for (int dc = 0; dc < DHEAD; dc += 16) {
        float4 q0 = *(const float4*)(qbase + (size_t)(i0+qi)*DHEAD + dc + qk);
        float4 q1 = *(const float4*)(qbase + (size_t)(i0+qi)*DHEAD + dc + qk + 4);
        Qs[qk+0][qi]=q0.x; Qs[qk+1][qi]=q0.y; Qs[qk+2][qi]=q0.z; Qs[qk+3][qi]=q0.w;
        Qs[qk+4][qi]=q1.x; Qs[qk+5][qi]=q1.y; Qs[qk+6][qi]=q1.z; Qs[qk+7][qi]=q1.w;

        float4 k0 = *(const float4*)(kbase + (size_t)(i0+j0+kr)*DHEAD + dc + kk8);
        float4 k1 = *(const float4*)(kbase + (size_t)(i0+j0+kr)*DHEAD + dc + kk8 + 4);
        Ks[kk8+0][kr]=k0.x; Ks[kk8+1][kr]=k0.y; Ks[kk8+2][kr]=k0.z; Ks[kk8+3][kr]=k0.w;
        Ks[kk8+4][kr]=k1.x; Ks[kk8+5][kr]=k1.y; Ks[kk8+6][kr]=k1.z; Ks[kk8+7][kr]=k1.w;
        if (tid < 128) {
            const int kr2 = 128 + (tid >> 1);
            const int kb2 = (tid & 1) * 8;
            float4 m0v = *(const float4*)(kbase + (size_t)(i0+j0+kr2)*DHEAD + dc + kb2);
            float4 m1v = *(const float4*)(kbase + (size_t)(i0+j0+kr2)*DHEAD + dc + kb2 + 4);
            Ks[kb2+0][kr2]=m0v.x; Ks[kb2+1][kr2]=m0v.y; Ks[kb2+2][kr2]=m0v.z; Ks[kb2+3][kr2]=m0v.w;
            Ks[kb2+4][kr2]=m1v.x; Ks[kb2+5][kr2]=m1v.y; Ks[kb2+6][kr2]=m1v.z; Ks[kb2+7][kr2]=m1v.w;
        }
        *(float4*)&Ps[pk][pj] = *(const float4*)(pos + (size_t)(dc + pk) * SEQ_L + j0 + pj);
        __syncthreads();

        const int base = ty*8 + tx*4;
#pragma unroll
        for (int kk = 0; kk < 16; kk++) {
            float4 a0 = *(const float4*)&Qs[kk][ty*8];
            float4 a1 = *(const float4*)&Qs[kk][ty*8+4];
            float4 p4 = *(const float4*)&Ps[kk][tx*4];
            float4 kA = *(const float4*)&Ks[kk][base];
            float4 kB = *(const float4*)&Ks[kk][base+4];
            float4 kC = *(const float4*)&Ks[kk][base+8];
            float q8[8] = {a0.x,a0.y,a0.z,a0.w,a1.x,a1.y,a1.z,a1.w};
            float pr[4] = {p4.x,p4.y,p4.z,p4.w};
            float kv[12] = {kA.x,kA.y,kA.z,kA.w,kB.x,kB.y,kB.z,kB.w,
                            kC.x,kC.y,kC.z,kC.w};
#pragma unroll
            for (int i = 0; i < 8; i++)
#pragma unroll
                for (int j = 0; j < 4; j++)
                    acc[i][j] = fmaf(q8[i], kv[i+j] + pr[j], acc[i][j]);
        }
        __syncthreads();
    }
    const float scale = 1.0f / 32.0f;
#pragma unroll
    for (int i = 0; i < 8; i++) {
        const int row = i0 + ty*8 + i;
        *(float4*)(g_s + ((size_t)bh * SEQ_M + row) * SEQ_L + j0 + tx*4) =
            make_float4(acc[i][0]*scale, acc[i][1]*scale, acc[i][2]*scale, acc[i][3]*scale);
    }
}

// ---------------- softmax: one warp per row (no barriers, no smem) -------------------
__global__ void __launch_bounds__(256) k_softmax()
{
    const int lane = threadIdx.x & 31;
    const size_t row = (size_t)blockIdx.x * 8 + (threadIdx.x >> 5);
    float* p = g_s + row * SEQ_L;

    float4 v[8];
#pragma unroll
    for (int i = 0; i < 8; i++)
        v[i] = *(const float4*)(p + i*128 + lane*4);

    float mx = -1e30f;
#pragma unroll
    for (int i = 0; i < 8; i++)
        mx = fmaxf(mx, fmaxf(fmaxf(v[i].x, v[i].y), fmaxf(v[i].z, v[i].w)));
#pragma unroll
    for (int o = 16; o; o >>= 1)
        mx = fmaxf(mx, __shfl_xor_sync(0xffffffffu, mx, o));

    float s = 0.f;
#pragma unroll
    for (int i = 0; i < 8; i++) {
        v[i].x = __expf(v[i].x - mx);
        v[i].y = __expf(v[i].y - mx);
        v[i].z = __expf(v[i].z - mx);
        v[i].w = __expf(v[i].w - mx);
        s += v[i].x + v[i].y + v[i].z + v[i].w;
    }
#pragma unroll
    for (int o = 16; o; o >>= 1)
        s += __shfl_xor_sync(0xffffffffu, s, o);
    const float inv = 1.0f / s;

#pragma unroll
    for (int i = 0; i < 8; i++)
        *(float4*)(p + i*128 + lane*4) = make_float4(
            v[i].x*inv, v[i].y*inv, v[i].z*inv, v[i].w*inv);
}

// ---------------- banded AV v2 (proven R11) -------------------------------------------
__global__ void __launch_bounds__(256) k_av()
{
    __shared__ float As2[16][128];
    __shared__ float Vs[16][64];
    const int bh = blockIdx.z;
    const int i0 = blockIdx.y * 128;
    const int d0 = blockIdx.x * 64;
    const int tid = threadIdx.x, ty = tid >> 4, tx = tid & 15;

    const float* abase = g_s + (size_t)bh * SEQ_M * SEQ_L;
    const float* vbase = g_v + (size_t)bh * LT * DHEAD;

    const int ail = tid >> 1;
    const int ar8 = (tid & 1) * 8;
    const float* arow_ptr = abase + (size_t)(i0 + ail) * SEQ_L;
    const int vr = tid >> 4, vd4 = (tid & 15) * 4;

    float acc[8][4] = {};
    for (int ch = 0; ch < (128 + SEQ_L) / 16; ch++) {
        const int ch16 = ch * 16;
        const int r0c = i0 + ch16;
#pragma unroll
        for (int u = 0; u < 8; u++) {
            const int rr = ar8 + u;
            const int j = ch16 + rr - ail;
            As2[rr][ail] = (j >= 0 && j < SEQ_L) ? arow_ptr[j] : 0.0f;
        }
        *(float4*)&Vs[vr][vd4] =
            *(const float4*)(vbase + (size_t)(r0c + vr) * DHEAD + d0 + vd4);
        __syncthreads();
#pragma unroll
        for (int rr = 0; rr < 16; rr++) {
            float4 a0 = *(const float4*)&As2[rr][ty*8];
            float4 a1 = *(const float4*)&As2[rr][ty*8+4];
            float4 v4 = *(const float4*)&Vs[rr][tx*4];
            float a8[8] = {a0.x,a0.y,a0.z,a0.w,a1.x,a1.y,a1.z,a1.w};
            float vv[4] = {v4.x,v4.y,v4.z,v4.w};
#pragma unroll
            for (int i = 0; i < 8; i++)
#pragma unroll
                for (int j = 0; j < 4; j++)
                    acc[i][j] = fmaf(a8[i], vv[j], acc[i][j]);
        }
        __syncthreads();
    }
    const int b = bh >> 3, nh = bh & 7;
#pragma unroll
    for (int i = 0; i < 8; i++) {
        const int row = i0 + ty*8 + i;
        *(float4*)(g_ao + ((size_t)(b * SEQ_M + row)) * HDIM + nh * DHEAD + d0 + tx*4) =
            make_float4(acc[i][0], acc[i][1], acc[i][2], acc[i][3]);
    }
}

// ---------------- Wo projection + residual (tf32 tensor, deep-k) ----------------------
__global__ void __launch_bounds__(256) k_wo(const float* __restrict__ Wo,
                                            const float* __restrict__ h)
{
    G32_DECLS
    const int m0 = blockIdx.y * 128, n0 = blockIdx.x * 128;

    const float* aptr = g_ao + (size_t)(m0 + alm) * HDIM;
    const float* bptr = Wo + n0 + bln;

    G32_PROLOGUE(HDIM, true)
    G32_LOOP(HDIM/32, HDIM, true)

#pragma unroll
    for (int mt = 0; mt < 2; mt++) {
        const int r0 = m0 + wm*32 + mt*16 + fg;
        const int r1 = r0 + 8;
#pragma unroll
        for (int nt = 0; nt < 8; nt++) {
            const int col = n0 + wn*64 + nt*8 + fc*2;
            float2 h0 = *(const float2*)(h + (size_t)r0 * HDIM + col);
            float2 h1 = *(const float2*)(h + (size_t)r1 * HDIM + col);
            *(float2*)(g_t1 + (size_t)r0 * HDIM + col) =
                make_float2(acc[mt][nt][0] + h0.x, acc[mt][nt][1] + h0.y);
            *(float2*)(g_t1 + (size_t)r1 * HDIM + col) =
                make_float2(acc[mt][nt][2] + h1.x, acc[mt][nt][3] + h1.y);
        }
    }
}

// ---------------- fused LN1 + gate ------------------------------------------------------
__global__ void __launch_bounds__(256) k_ln1gate(
    const float* __restrict__ g, const float* __restrict__ b,
    const float* __restrict__ gw, const float* __restrict__ gb)
{
    __shared__ float sbuf[8];
    __shared__ float xs[HDIM];
    __shared__ float lg[NEXP];
    const int row = blockIdx.x;
    const int c0 = threadIdx.x * 4;
    float4 xv = *(const float4*)(g_t1 + (size_t)row * HDIM + c0);
    float s  = xv.x + xv.y + xv.z + xv.w;
    float s2 = xv.x*xv.x + xv.y*xv.y + xv.z*xv.z + xv.w*xv.w;
    s  = blk_sum8(s,  sbuf);
    s2 = blk_sum8(s2, sbuf);
    const float mu = s * (1.0f / HDIM);
    const float var = s2 * (1.0f / HDIM) - mu * mu;
    const float inv = rsqrtf(var + 1e-5f);
    float4 gv = *(const float4*)(g + c0);
    float4 bv = *(const float4*)(b + c0);
    float4 r = make_float4(
        (xv.x - mu) * inv * gv.x + bv.x,
        (xv.y - mu) * inv * gv.y + bv.y,
        (xv.z - mu) * inv * gv.z + bv.z,
        (xv.w - mu) * inv * gv.w + bv.w);
    *(float4*)(g_h1 + (size_t)row * HDIM + c0) = r;
    *(float4*)&xs[c0] = r;
    __syncthreads();

    const int w = threadIdx.x >> 5, lane = threadIdx.x & 31;
    float sg = 0.0f;
    for (int hh = lane; hh < HDIM; hh += 32)
        sg = fmaf(xs[hh], gw[hh * NEXP + w], sg);
#pragma unroll
    for (int o = 16; o; o >>= 1) sg += __shfl_xor_sync(0xffffffffu, sg, o);
    if (lane == 0) lg[w] = sg + gb[w];
    __syncthreads();
    if (threadIdx.x == 0) {
        int i0 = 0;
        for (int e = 1; e < NEXP; e++) if (lg[e] > lg[i0]) i0 = e;
        int i1 = -1;
        for (int e = 0; e < NEXP; e++) {
            if (e == i0) continue;
            if (i1 < 0 || lg[e] > lg[i1]) i1 = e;
        }
        const float e1 = __expf(lg[i1] - lg[i0]);
        const float den = 1.0f / (1.0f + e1);
        g_top_e[2*row]   = i0; g_top_e[2*row+1] = i1;
        g_top_w[2*row]   = den;
        g_top_w[2*row+1] = e1 * den;
        atomicAdd(&g_cnt[i0], 1);
        atomicAdd(&g_cnt[i1], 1);
    }
}

// ---------------- scatter with inline scan (k_scan folded in) ---------------------------
__global__ void __launch_bounds__(256) k_scatter()
{
    int offl[NEXP];
    {
        int s = 0;
#pragma unroll
        for (int e = 0; e < NEXP; e++) { offl[e] = s; s += g_cnt[e]; }
    }
    if (blockIdx.x == 0 && threadIdx.x == 0) {
#pragma unroll
        for (int e = 0; e < NEXP; e++) g_off[e] = offl[e];
    }
    const int t = blockIdx.x * 256 + threadIdx.x;
    if (t >= NTOK) return;
#pragma unroll
    for (int k = 0; k < 2; k++) {
        const int e = g_top_e[2*t + k];
        const int p = atomicAdd(&g_cur[e], 1);
        const int pos = offl[e] + p;
        g_slot_token[pos] = t;
        g_slot_w[pos] = g_top_w[2*t + k];
        g_token_slot[2*t + k] = pos;
    }
}

// ---------------- MoE GEMM1 (tf32 tensor, deep-k) ----------------------------------------
__global__ void __launch_bounds__(256) k_moe1(const float* __restrict__ w1,
                                              const float* __restrict__ b1)
{
    const int e = blockIdx.z;
    const int cnt = g_cnt[e];
    const int r0b = blockIdx.y * 128;
    if (r0b >= cnt) return;
    const int off = g_off[e];

    __shared__ int toks[128];
    G32_DECLS
    const int n0 = blockIdx.x * 128;

    if (tid < 128) {
        const int r = r0b + tid;
        toks[tid] = (r < cnt) ? g_slot_token[off + r] : -1;
    }
    __syncthreads();
    const int tok = toks[alm];
    const bool aval = (tok >= 0);
    const float* aptr = g_h1 + (size_t)(aval ? tok : 0) * HDIM;
    const float* bptr = w1 + (size_t)e * HDIM * FDIM + n0 + bln;

    G32_PROLOGUE(FDIM, aval)
    G32_LOOP(HDIM/32, FDIM, aval)

#pragma unroll
    for (int mt = 0; mt < 2; mt++) {
        const int r0 = r0b + wm*32 + mt*16 + fg;
        const int r1 = r0 + 8;
#pragma unroll
        for (int nt = 0; nt < 8; nt++) {
            const int col = n0 + wn*64 + nt*8 + fc*2;
            float2 bb = *(const float2*)(b1 + (size_t)e * FDIM + col);
            if (r0 < cnt)
                *(float2*)(g_hidden + (size_t)(off + r0) * FDIM + col) =
                    make_float2(fmaxf(acc[mt][nt][0] + bb.x, 0.f),
                                fmaxf(acc[mt][nt][1] + bb.y, 0.f));
            if (r1 < cnt)
                *(float2*)(g_hidden + (size_t)(off + r1) * FDIM + col) =
                    make_float2(fmaxf(acc[mt][nt][2] + bb.x, 0.f),
                                fmaxf(acc[mt][nt][3] + bb.y, 0.f));
        }
    }
}

// ---------------- MoE GEMM2 (tf32 tensor, deep-k) ------------------------------------------
__global__ void __launch_bounds__(256) k_moe2(const float* __restrict__ w2,
                                              const float* __restrict__ b2)
{
    const int e = blockIdx.z;
    const int cnt = g_cnt[e];
    const int r0b = blockIdx.y * 128;
    if (r0b >= cnt) return;
    const int off = g_off[e];

    G32_DECLS
    const int n0 = blockIdx.x * 128;

    const int r = r0b + alm;
    const bool aval = (r < cnt);
    const float* aptr = g_hidden + (size_t)(off + (aval ? r : 0)) * FDIM;
    const float* bptr = w2 + (size_t)e * FDIM * HDIM + n0 + bln;

    G32_PROLOGUE(HDIM, aval)
    G32_LOOP(FDIM/32, HDIM, aval)

#pragma unroll
    for (int mt = 0; mt < 2; mt++) {
        const int r0 = r0b + wm*32 + mt*16 + fg;
        const int r1 = r0 + 8;
#pragma unroll
        for (int nt = 0; nt < 8; nt++) {
            const int col = n0 + wn*64 + nt*8 + fc*2;
            float2 bb = *(const float2*)(b2 + (size_t)e * HDIM + col);
            if (r0 < cnt)
                *(float2*)(g_y + (size_t)(off + r0) * HDIM + col) =
                    make_float2(acc[mt][nt][0] + bb.x, acc[mt][nt][1] + bb.y);
            if (r1 < cnt)
                *(float2*)(g_y + (size_t)(off + r1) * HDIM + col) =
                    make_float2(acc[mt][nt][2] + bb.x, acc[mt][nt][3] + bb.y);
        }
    }
}

// ---------------- combine + LN2 -----------------------------------------------------------
__global__ void __launch_bounds__(256) k_combine(const float* __restrict__ mom_in,
                                                 const float* __restrict__ g,
                                                 const float* __restrict__ b,
                                                 float* __restrict__ out)
{
    __shared__ float sbuf[8];
    const int t = blockIdx.x;
    const int s0 = g_token_slot[2*t], s1 = g_token_slot[2*t + 1];
    const float w0 = g_slot_w[s0], w1 = g_slot_w[s1];
    const int c0 = threadIdx.x * 4;

    float4 h1v = *(const float4*)(g_h1 + (size_t)t * HDIM + c0);
    float4 mv  = *(const float4*)(mom_in + (size_t)t * HDIM + c0);
    float4 y0  = *(const float4*)(g_y + (size_t)s0 * HDIM + c0);
    float4 y1  = *(const float4*)(g_y + (size_t)s1 * HDIM + c0);

    float momn[4], x[4];
    momn[0] = 0.7f*mv.x + w0*y0.x + w1*y1.x;
    momn[1] = 0.7f*mv.y + w0*y0.y + w1*y1.y;
    momn[2] = 0.7f*mv.z + w0*y0.z + w1*y1.z;
    momn[3] = 0.7f*mv.w + w0*y0.w + w1*y1.w;
    x[0] = h1v.x - momn[0]; x[1] = h1v.y - momn[1];
    x[2] = h1v.z - momn[2]; x[3] = h1v.w - momn[3];

    float s  = x[0] + x[1] + x[2] + x[3];
    float s2 = x[0]*x[0] + x[1]*x[1] + x[2]*x[2] + x[3]*x[3];
    s  = blk_sum8(s,  sbuf);
    s2 = blk_sum8(s2, sbuf);
    const float mu = s * (1.0f / HDIM);
    const float var = s2 * (1.0f / HDIM) - mu * mu;
    const float inv = rsqrtf(var + 1e-5f);
    float4 gv = *(const float4*)(g + c0);
    float4 bv = *(const float4*)(b + c0);

    *(float4*)(out + (size_t)t * HDIM + c0) = make_float4(
        (x[0] - mu) * inv * gv.x + bv.x,
        (x[1] - mu) * inv * gv.y + bv.y,
        (x[2] - mu) * inv * gv.z + bv.z,
        (x[3] - mu) * inv * gv.w + bv.w);
    *(float4*)(out + (size_t)NTOK * HDIM + (size_t)t * HDIM + c0) =
        make_float4(momn[0], momn[1], momn[2], momn[3]);
}

// ---------------- launch ---------------------------------------------------------------------
extern "C" void kernel_launch(void* const* d_in, const int* in_sizes, int n_in,
                              void* d_out, int out_size)
{
    const float* h       = (const float*)d_in[0];
    const float* h_cache = (const float*)d_in[1];
    const float* pos     = (const float*)d_in[2];
    const float* mom     = (const float*)d_in[3];
    const float* Wq      = (const float*)d_in[4];
    const float* Wk      = (const float*)d_in[5];
    const float* Wv      = (const float*)d_in[6];
    const float* Wo      = (const float*)d_in[7];
    const float* gate_w  = (const float*)d_in[8];
    const float* gate_b  = (const float*)d_in[9];
    const float* w1      = (const float*)d_in[10];
    const float* b1      = (const float*)d_in[11];
    const float* w2      = (const float*)d_in[12];
    const float* b2      = (const float*)d_in[13];
    const float* ln1g    = (const float*)d_in[14];
    const float* ln1b    = (const float*)d_in[15];
    const float* ln2g    = (const float*)d_in[16];
    const float* ln2b    = (const float*)d_in[17];
    float* out = (float*)d_out;

    cudaFuncSetAttribute(k_qkv,  cudaFuncAttributeMaxDynamicSharedMemorySize, G32_SMEM_BYTES);
    cudaFuncSetAttribute(k_wo,   cudaFuncAttributeMaxDynamicSharedMemorySize, G32_SMEM_BYTES);
    cudaFuncSetAttribute(k_moe1, cudaFuncAttributeMaxDynamicSharedMemorySize, G32_SMEM_BYTES);
    cudaFuncSetAttribute(k_moe2, cudaFuncAttributeMaxDynamicSharedMemorySize, G32_SMEM_BYTES);

    k_init<<<1, 32>>>();
    k_qkv<<<1280, 256, G32_SMEM_BYTES>>>(h, h_cache, Wq, Wk, Wv);
    k_scores<<<dim3(SEQ_L/64, SEQ_M/128, NBH), 256>>>(pos);
    k_softmax<<<NBH*SEQ_M/8, 256>>>();
    k_av<<<dim3(DHEAD/64, SEQ_M/128, NBH), 256>>>();
    k_wo<<<dim3(HDIM/128, NTOK/128), 256, G32_SMEM_BYTES>>>(Wo, h);
    k_ln1gate<<<NTOK, 256>>>(ln1g, ln1b, gate_w, gate_b);
    k_scatter<<<NTOK/256, 256>>>();
    k_moe1<<<dim3(FDIM/128, NSLOT/128, NEXP), 256, G32_SMEM_BYTES>>>(w1, b1);
    k_moe2<<<dim3(HDIM/128, NSLOT/128, NEXP), 256, G32_SMEM_BYTES>>>(w2, b2);
    k_combine<<<NTOK, 256>>>(mom, ln2g, ln2b, out);
}

// round 16
// speedup vs baseline: 1.1086x; 1.0093x over previous
#include <cuda_runtime.h>
#include <math.h>

#define BATCH 4
#define SEQ_M 1024
#define HDIM  1024
#define NHEAD 8
#define DHEAD 128
#define SEQ_L 1024
#define NEXP  8
#define FDIM  4096
#define NTOK  (BATCH*SEQ_M)
#define NBH   (BATCH*NHEAD)
#define LT    (SEQ_L+SEQ_M)
#define NSLOT (NTOK*2)

// ---------------- scratch (device globals) -------------------------------------
__device__ float g_q[(size_t)NBH*SEQ_M*DHEAD];
__device__ float g_k[(size_t)NBH*LT*DHEAD];
__device__ float g_v[(size_t)NBH*LT*DHEAD];
__device__ float g_s[(size_t)NBH*SEQ_M*SEQ_L];
__device__ float g_ao[(size_t)NTOK*HDIM];
__device__ float g_t1[(size_t)NTOK*HDIM];
__device__ float g_h1[(size_t)NTOK*HDIM];
__device__ float g_hidden[(size_t)NSLOT*FDIM];
__device__ float g_y[(size_t)NSLOT*HDIM];
__device__ int   g_cnt[NEXP];
__device__ int   g_cur[NEXP];
__device__ int   g_off[NEXP];
__device__ int   g_slot_token[NSLOT];
__device__ float g_slot_w[NSLOT];
__device__ int   g_token_slot[NTOK*2];
__device__ int   g_top_e[NTOK*2];
__device__ float g_top_w[NTOK*2];

// ---------------- tf32 helpers -----------------------------------------------
__device__ __forceinline__ unsigned f2tf(float x)
{
    unsigned y;
    asm("cvt.rna.tf32.f32 %0, %1;" : "=r"(y) : "f"(x));
    return y;
}
__device__ __forceinline__ float4 tf4(float4 v)
{
    return make_float4(__uint_as_float(f2tf(v.x)), __uint_as_float(f2tf(v.y)),
                       __uint_as_float(f2tf(v.z)), __uint_as_float(f2tf(v.w)));
}

#define MMA_TF32(d0,d1,d2,d3,a0,a1,a2,a3,b0,b1)                             \
    asm volatile("mma.sync.aligned.m16n8k8.row.col.f32.tf32.tf32.f32 "      \
        "{%0,%1,%2,%3}, {%4,%5,%6,%7}, {%8,%9}, {%0,%1,%2,%3};"             \
        : "+f"(d0),"+f"(d1),"+f"(d2),"+f"(d3)                               \
        : "r"(a0),"r"(a1),"r"(a2),"r"(a3),"r"(b0),"r"(b1));

// ---------------- tf32 128x128x32 GEMM (deep kblock, phase-split prefetch) ------
#define G32_SMEM_BYTES 69632

#define G32_DECLS                                                            \
    const int tid = threadIdx.x, lane = tid & 31, warp = tid >> 5;           \
    const int wm = warp >> 1, wn = warp & 1;                                 \
    const int fg = lane >> 2, fc = lane & 3;                                 \
    const int alm = tid & 127, kslot = (tid >> 7) * 16;                      \
    const int blkr = tid >> 5, bln = lane * 4;                               \
    extern __shared__ float smp[];                                           \
    const float4 z4 = make_float4(0.f, 0.f, 0.f, 0.f);                       \
    (void)z4;

#define AS(buf,k,m) smp[(buf)*4352 + (k)*136 + (m)]
#define BS(buf,k,n) smp[8704 + (buf)*4352 + (k)*136 + (n)]

#define G32_STA(buf, kbase, P0, P1) {                                        \
    const float* _q0 = (const float*)&(P0);                                  \
    const float* _q1 = (const float*)&(P1);                                  \
    _Pragma("unroll")                                                        \
    for (int i = 0; i < 4; i++) {                                            \
        AS(buf, (kbase)+i,   alm) = __uint_as_float(f2tf(_q0[i]));           \
        AS(buf, (kbase)+4+i, alm) = __uint_as_float(f2tf(_q1[i]));           \
    } }

#define G32_COMP8(cur, k8) {                                                 \
    unsigned afr[2][4], bfr[8][2];                                           \
    _Pragma("unroll")                                                        \
    for (int mt = 0; mt < 2; mt++) {                                         \
        const int mr = wm*32 + mt*16 + fg;                                   \
        afr[mt][0] = __float_as_uint(AS(cur, (k8)+fc,   mr));                \
        afr[mt][1] = __float_as_uint(AS(cur, (k8)+fc,   mr+8));              \
        afr[mt][2] = __float_as_uint(AS(cur, (k8)+fc+4, mr));                \
        afr[mt][3] = __float_as_uint(AS(cur, (k8)+fc+4, mr+8));              \
    }                                                                        \
    _Pragma("unroll")                                                        \
    for (int nt = 0; nt < 8; nt++) {                                         \
        const int nc = wn*64 + nt*8 + fg;                                    \
        bfr[nt][0] = __float_as_uint(BS(cur, (k8)+fc,   nc));                \
        bfr[nt][1] = __float_as_uint(BS(cur, (k8)+fc+4, nc));                \
    }                                                                        \
    _Pragma("unroll")                                                        \
    for (int mt = 0; mt < 2; mt++)                                           \
    _Pragma("unroll")                                                        \
    for (int nt = 0; nt < 8; nt++)                                           \
        MMA_TF32(acc[mt][nt][0],acc[mt][nt][1],acc[mt][nt][2],acc[mt][nt][3],\
                 afr[mt][0],afr[mt][1],afr[mt][2],afr[mt][3],                \
                 bfr[nt][0],bfr[nt][1]); }

#define G32_PROLOGUE(LDB, AVALID) {                                          \
    float4 a0 = z4, a1 = z4;                                                 \
    if (AVALID) { a0 = *(const float4*)(aptr + kslot);                       \
                  a1 = *(const float4*)(aptr + kslot + 4); }                 \
    float4 b0 = *(const float4*)(bptr + (size_t)blkr * (LDB));               \
    float4 b1 = *(const float4*)(bptr + (size_t)(blkr + 8) * (LDB));         \
    G32_STA(0, kslot, a0, a1)                                                \
    *(float4*)&BS(0, blkr,   bln) = tf4(b0);                                 \
    *(float4*)&BS(0, blkr+8, bln) = tf4(b1);                                 \
    if (AVALID) { a0 = *(const float4*)(aptr + kslot + 8);                   \
                  a1 = *(const float4*)(aptr + kslot + 12); }                \
    b0 = *(const float4*)(bptr + (size_t)(blkr + 16) * (LDB));               \
    b1 = *(const float4*)(bptr + (size_t)(blkr + 24) * (LDB));               \
    G32_STA(0, kslot + 8, a0, a1)                                            \
    *(float4*)&BS(0, blkr+16, bln) = tf4(b0);                                \
    *(float4*)&BS(0, blkr+24, bln) = tf4(b1);                                \
    }                                                                        \
    __syncthreads();

#define G32_LOOP(NKB, LDB, AVALID)                                           \
    float acc[2][8][4] = {};                                                 \
    for (int kb = 0; kb < (NKB); kb++) {                                     \
        const int cur = kb & 1;                                              \
        const bool pf = (kb + 1 < (NKB));                                    \
        float4 a0 = z4, a1 = z4, b0 = z4, b1 = z4;                           \
        if (pf) {                                                            \
            if (AVALID) {                                                    \
                a0 = *(const float4*)(aptr + (kb+1)*32 + kslot);             \
                a1 = *(const float4*)(aptr + (kb+1)*32 + kslot + 4);         \
            }                                                                \
            b0 = *(const float4*)(bptr + (size_t)((kb+1)*32 + blkr)*(LDB));  \
            b1 = *(const float4*)(bptr + (size_t)((kb+1)*32 + blkr+8)*(LDB));\
        }                                                                    \
        G32_COMP8(cur, 0)                                                    \
        G32_COMP8(cur, 8)                                                    \
        if (pf) {                                                            \
            const int nxt = cur ^ 1;                                         \
            G32_STA(nxt, kslot, a0, a1)                                      \
            *(float4*)&BS(nxt, blkr,   bln) = tf4(b0);                       \
            *(float4*)&BS(nxt, blkr+8, bln) = tf4(b1);                       \
            if (AVALID) {                                                    \
                a0 = *(const float4*)(aptr + (kb+1)*32 + kslot + 8);         \
                a1 = *(const float4*)(aptr + (kb+1)*32 + kslot + 12);        \
            }                                                                \
            b0 = *(const float4*)(bptr + (size_t)((kb+1)*32 + blkr+16)*(LDB));\
            b1 = *(const float4*)(bptr + (size_t)((kb+1)*32 + blkr+24)*(LDB));\
        }                                                                    \
        G32_COMP8(cur, 16)                                                   \
        G32_COMP8(cur, 24)                                                   \
        if (pf) {                                                            \
            const int nxt = cur ^ 1;                                         \
            G32_STA(nxt, kslot + 8, a0, a1)                                  \
            *(float4*)&BS(nxt, blkr+16, bln) = tf4(b0);                      \
            *(float4*)&BS(nxt, blkr+24, bln) = tf4(b1);                      \
        }                                                                    \
        __syncthreads();                                                     \
    }

// ---------------- block reductions (256 threads / 8 warps) --------------------
__device__ __forceinline__ float blk_sum8(float v, float* sbuf)
{
    const int lane = threadIdx.x & 31, w = threadIdx.x >> 5;
#pragma unroll
    for (int o = 16; o; o >>= 1) v += __shfl_xor_sync(0xffffffffu, v, o);
    __syncthreads();
    if (lane == 0) sbuf[w] = v;
    __syncthreads();
    return sbuf[0]+sbuf[1]+sbuf[2]+sbuf[3]+sbuf[4]+sbuf[5]+sbuf[6]+sbuf[7];
}

// ---------------- init ----------------------------------------------------------
__global__ void k_init()
{
    int t = threadIdx.x;
    if (t < NEXP) { g_cnt[t] = 0; g_cur[t] = 0; }
}

// ---------------- fused QKV projections (one launch, tail-filled) -----------------
__global__ void __launch_bounds__(256) k_qkv(
    const float* __restrict__ h, const float* __restrict__ h_cache,
    const float* __restrict__ Wq, const float* __restrict__ Wk,
    const float* __restrict__ Wv)
{
    G32_DECLS
    const int bid = blockIdx.x;
    int job, mb, nb;
    if (bid < 256)      { job = 0; mb = bid >> 3;          nb = bid & 7; }
    else if (bid < 768) { job = 1; mb = (bid - 256) >> 3;  nb = bid & 7; }
    else                { job = 2; mb = (bid - 768) >> 3;  nb = bid & 7; }
    const int m0 = mb * 128, n0 = nb * 128;
    const float* W = (job == 0) ? Wq : (job == 1) ? Wk : Wv;

    const int arow = m0 + alm;
    const float* aptr;
    if (job == 0) {
        aptr = h + (size_t)arow * HDIM;
    } else {
        const int b = arow >> 11, t = arow & 2047;
        aptr = (t < SEQ_L) ? (h_cache + ((size_t)b * SEQ_L + t) * HDIM)
                           : (h + ((size_t)b * SEQ_M + (t - SEQ_L)) * HDIM);
    }
    const float* bptr = W + n0 + bln;

    G32_PROLOGUE(HDIM, true)
    G32_LOOP(HDIM/32, HDIM, true)

#pragma unroll
    for (int mt = 0; mt < 2; mt++) {
        const int r0 = m0 + wm*32 + mt*16 + fg;
        const int r1 = r0 + 8;
#pragma unroll
        for (int nt = 0; nt < 8; nt++) {
            const int col = n0 + wn*64 + nt*8 + fc*2;
            const int nh = col >> 7, d = col & 127;
            float *o0, *o1;
            if (job == 0) {
                int b = r0 >> 10, mm = r0 & 1023;
                o0 = g_q + (((size_t)(b*NHEAD + nh) * SEQ_M + mm) * DHEAD + d);
                b = r1 >> 10; mm = r1 & 1023;
                o1 = g_q + (((size_t)(b*NHEAD + nh) * SEQ_M + mm) * DHEAD + d);
            } else {
                float* base = (job == 1) ? g_k : g_v;
                int b = r0 >> 11, t = r0 & 2047;
                o0 = base + (((size_t)(b*NHEAD + nh) * LT + t) * DHEAD + d);
                b = r1 >> 11; t = r1 & 2047;
                o1 = base + (((size_t)(b*NHEAD + nh) * LT + t) * DHEAD + d);
            }
            *(float2*)o0 = make_float2(acc[mt][nt][0], acc[mt][nt][1]);
            *(float2*)o1 = make_float2(acc[mt][nt][2], acc[mt][nt][3]);
        }
    }
}

// ---------------- banded scores v2 (proven R11) -------------------------------------
__global__ void __launch_bounds__(256) k_scores(const float* __restrict__ pos)
{
    __shared__ float Qs[16][128];
    __shared__ float Ks[16][192];
    __shared__ float Ps[16][64];
    const int bh = blockIdx.z;
    const int i0 = blockIdx.y * 128, j0 = blockIdx.x * 64;
    const int tid = threadIdx.x, ty = tid >> 4, tx = tid & 15;

    const float* qbase = g_q + (size_t)bh * SEQ_M * DHEAD;
    const float* kbase = g_k + (size_t)bh * LT * DHEAD;

    const int qi = tid >> 1, qk = (tid & 1) * 8;
    const int pk = tid >> 4, pj = (tid & 15) * 4;
    const int kr = tid >> 1, kk8 = (tid & 1) * 8;

    float acc[8][4] = {};
    for (int dc = 0; dc < DHEAD; dc += 16) {
        float4 q0 = *(const float4*)(qbase + (size_t)(i0+qi)*DHEAD + dc + qk);
        float4 q1 = *(const float4*)(qbase + (size_t)(i0+qi)*DHEAD + dc + qk + 4);
        Qs[qk+0][qi]=q0.x; Qs[qk+1][qi]=q0.y; Qs[qk+2][qi]=q0.z; Qs[qk+3][qi]=q0.w;
        Qs[qk+4][qi]=q1.x; Qs[qk+5][qi]=q1.y; Qs[qk+6][qi]=q1.z; Qs[qk+7][qi]=q1.w;

        float4 k0 = *(const float4*)(kbase + (size_t)(i0+j0+kr)*DHEAD + dc + kk8);
        float4 k1 = *(const float4*)(kbase + (size_t)(i0+j0+kr)*DHEAD + dc + kk8 + 4);
        Ks[kk8+0][kr]=k0.x; Ks[kk8+1][kr]=k0.y; Ks[kk8+2][kr]=k0.z; Ks[kk8+3][kr]=k0.w;
        Ks[kk8+4][kr]=k1.x; Ks[kk8+5][kr]=k1.y; Ks[kk8+6][kr]=k1.z; Ks[kk8+7][kr]=k1.w;
        if (tid < 128) {
            const int kr2 = 128 + (tid >> 1);
            const int kb2 = (tid & 1) * 8;
            float4 m0v = *(const float4*)(kbase + (size_t)(i0+j0+kr2)*DHEAD + dc + kb2);
            float4 m1v = *(const float4*)(kbase + (size_t)(i0+j0+kr2)*DHEAD + dc + kb2 + 4);
            Ks[kb2+0][kr2]=m0v.x; Ks[kb2+1][kr2]=m0v.y; Ks[kb2+2][kr2]=m0v.z; Ks[kb2+3][kr2]=m0v.w;
            Ks[kb2+4][kr2]=m1v.x; Ks[kb2+5][kr2]=m1v.y; Ks[kb2+6][kr2]=m1v.z; Ks[kb2+7][kr2]=m1v.w;
        }
        *(float4*)&Ps[pk][pj] = *(const float4*)(pos + (size_t)(dc + pk) * SEQ_L + j0 + pj);
        __syncthreads();

        const int base = ty*8 + tx*4;
#pragma unroll
        for (int kk = 0; kk < 16; kk++) {
            float4 a0 = *(const float4*)&Qs[kk][ty*8];
            float4 a1 = *(const float4*)&Qs[kk][ty*8+4];
            float4 p4 = *(const float4*)&Ps[kk][tx*4];
            float4 kA = *(const float4*)&Ks[kk][base];
            float4 kB = *(const float4*)&Ks[kk][base+4];
            float4 kC = *(const float4*)&Ks[kk][base+8];
            float q8[8] = {a0.x,a0.y,a0.z,a0.w,a1.x,a1.y,a1.z,a1.w};
            float pr[4] = {p4.x,p4.y,p4.z,p4.w};
            float kv[12] = {kA.x,kA.y,kA.z,kA.w,kB.x,kB.y,kB.z,kB.w,
                            kC.x,kC.y,kC.z,kC.w};
#pragma unroll
            for (int i = 0; i < 8; i++)
#pragma unroll
                for (int j = 0; j < 4; j++)
                    acc[i][j] = fmaf(q8[i], kv[i+j] + pr[j], acc[i][j]);
        }
        __syncthreads();
    }
    const float scale = 1.0f / 32.0f;
#pragma unroll
    for (int i = 0; i < 8; i++) {
        const int row = i0 + ty*8 + i;
        *(float4*)(g_s + ((size_t)bh * SEQ_M + row) * SEQ_L + j0 + tx*4) =
            make_float4(acc[i][0]*scale, acc[i][1]*scale, acc[i][2]*scale, acc[i][3]*scale);
    }
}

// ---------------- softmax: one warp per row (no barriers, no smem) -------------------
__global__ void __launch_bounds__(256) k_softmax()
{
    const int lane = threadIdx.x & 31;
    const size_t row = (size_t)blockIdx.x * 8 + (threadIdx.x >> 5);
    float* p = g_s + row * SEQ_L;

    float4 v[8];
#pragma unroll
    for (int i = 0; i < 8; i++)
        v[i] = *(const float4*)(p + i*128 + lane*4);

    float mx = -1e30f;
#pragma unroll
    for (int i = 0; i < 8; i++)
        mx = fmaxf(mx, fmaxf(fmaxf(v[i].x, v[i].y), fmaxf(v[i].z, v[i].w)));
#pragma unroll
    for (int o = 16; o; o >>= 1)
        mx = fmaxf(mx, __shfl_xor_sync(0xffffffffu, mx, o));

    float s = 0.f;
#pragma unroll
    for (int i = 0; i < 8; i++) {
        v[i].x = __expf(v[i].x - mx);
        v[i].y = __expf(v[i].y - mx);
        v[i].z = __expf(v[i].z - mx);
        v[i].w = __expf(v[i].w - mx);
        s += v[i].x + v[i].y + v[i].z + v[i].w;
    }
#pragma unroll
    for (int o = 16; o; o >>= 1)
        s += __shfl_xor_sync(0xffffffffu, s, o);
    const float inv = 1.0f / s;

#pragma unroll
    for (int i = 0; i < 8; i++)
        *(float4*)(p + i*128 + lane*4) = make_float4(
            v[i].x*inv, v[i].y*inv, v[i].z*inv, v[i].w*inv);
}

// ---------------- banded AV v3: 128(i) x 128(d) tile, 8x8 microtile -------------------
__global__ void __launch_bounds__(256) k_av()
{
    __shared__ float As2[16][128];
    __shared__ float Vs[16][136];
    const int bh = blockIdx.y;
    const int i0 = blockIdx.x * 128;
    const int tid = threadIdx.x, ty = tid >> 4, tx = tid & 15;

    const float* abase = g_s + (size_t)bh * SEQ_M * SEQ_L;
    const float* vbase = g_v + (size_t)bh * LT * DHEAD;

    const int ail = tid >> 1;          // 0..127
    const int ar8 = (tid & 1) * 8;     // rr base
    const float* arow_ptr = abase + (size_t)(i0 + ail) * SEQ_L;
    const int vr = tid >> 4, vc = (tid & 15) * 8;

    float acc[8][8] = {};
    for (int ch = 0; ch < (128 + SEQ_L) / 16; ch++) {   // 72 chunks
        const int ch16 = ch * 16;
        const int r0c = i0 + ch16;
#pragma unroll
        for (int u = 0; u < 8; u++) {
            const int rr = ar8 + u;
            const int j = ch16 + rr - ail;
            As2[rr][ail] = (j >= 0 && j < SEQ_L) ? arow_ptr[j] : 0.0f;
        }
        const float* vrow = vbase + (size_t)(r0c + vr) * DHEAD + vc;
        *(float4*)&Vs[vr][vc]     = *(const float4*)(vrow);
        *(float4*)&Vs[vr][vc + 4] = *(const float4*)(vrow + 4);
        __syncthreads();
#pragma unroll
        for (int rr = 0; rr < 16; rr++) {
            float4 a0 = *(const float4*)&As2[rr][ty*8];
            float4 a1 = *(const float4*)&As2[rr][ty*8+4];
            float4 vA = *(const float4*)&Vs[rr][tx*8];
            float4 vB = *(const float4*)&Vs[rr][tx*8+4];
            float a8[8] = {a0.x,a0.y,a0.z,a0.w,a1.x,a1.y,a1.z,a1.w};
            float vv[8] = {vA.x,vA.y,vA.z,vA.w,vB.x,vB.y,vB.z,vB.w};
#pragma unroll
            for (int i = 0; i < 8; i++)
#pragma unroll
                for (int j = 0; j < 8; j++)
                    acc[i][j] = fmaf(a8[i], vv[j], acc[i][j]);
        }
        __syncthreads();
    }
    const int b = bh >> 3, nh = bh & 7;
#pragma unroll
    for (int i = 0; i < 8; i++) {
        const int row = i0 + ty*8 + i;
        float* o = g_ao + ((size_t)(b * SEQ_M + row)) * HDIM + nh * DHEAD + tx*8;
        *(float4*)o       = make_float4(acc[i][0], acc[i][1], acc[i][2], acc[i][3]);
        *(float4*)(o + 4) = make_float4(acc[i][4], acc[i][5], acc[i][6], acc[i][7]);
    }
}

// ---------------- Wo projection + residual (tf32 tensor, deep-k) ----------------------
__global__ void __launch_bounds__(256) k_wo(const float* __restrict__ Wo,
                                            const float* __restrict__ h)
{
    G32_DECLS
    const int m0 = blockIdx.y * 128, n0 = blockIdx.x * 128;

    const float* aptr = g_ao + (size_t)(m0 + alm) * HDIM;
    const float* bptr = Wo + n0 + bln;

    G32_PROLOGUE(HDIM, true)
    G32_LOOP(HDIM/32, HDIM, true)

#pragma unroll
    for (int mt = 0; mt < 2; mt++) {
        const int r0 = m0 + wm*32 + mt*16 + fg;
        const int r1 = r0 + 8;
#pragma unroll
        for (int nt = 0; nt < 8; nt++) {
            const int col = n0 + wn*64 + nt*8 + fc*2;
            float2 h0 = *(const float2*)(h + (size_t)r0 * HDIM + col);
            float2 h1 = *(const float2*)(h + (size_t)r1 * HDIM + col);
            *(float2*)(g_t1 + (size_t)r0 * HDIM + col) =
                make_float2(acc[mt][nt][0] + h0.x, acc[mt][nt][1] + h0.y);
            *(float2*)(g_t1 + (size_t)r1 * HDIM + col) =
                make_float2(acc[mt][nt][2] + h1.x, acc[mt][nt][3] + h1.y);
        }
    }
}

// ---------------- fused LN1 + gate ------------------------------------------------------
__global__ void __launch_bounds__(256) k_ln1gate(
    const float* __restrict__ g, const float* __restrict__ b,
    const float* __restrict__ gw, const float* __restrict__ gb)
{
    __shared__ float sbuf[8];
    __shared__ float xs[HDIM];
    __shared__ float lg[NEXP];
    const int row = blockIdx.x;
    const int c0 = threadIdx.x * 4;
    float4 xv = *(const float4*)(g_t1 + (size_t)row * HDIM + c0);
    float s  = xv.x + xv.y + xv.z + xv.w;
    float s2 = xv.x*xv.x + xv.y*xv.y + xv.z*xv.z + xv.w*xv.w;
    s  = blk_sum8(s,  sbuf);
    s2 = blk_sum8(s2, sbuf);
    const float mu = s * (1.0f / HDIM);
    const float var = s2 * (1.0f / HDIM) - mu * mu;
    const float inv = rsqrtf(var + 1e-5f);
    float4 gv = *(const float4*)(g + c0);
    float4 bv = *(const float4*)(b + c0);
    float4 r = make_float4(
        (xv.x - mu) * inv * gv.x + bv.x,
        (xv.y - mu) * inv * gv.y + bv.y,
        (xv.z - mu) * inv * gv.z + bv.z,
        (xv.w - mu) * inv * gv.w + bv.w);
    *(float4*)(g_h1 + (size_t)row * HDIM + c0) = r;
    *(float4*)&xs[c0] = r;
    __syncthreads();

    const int w = threadIdx.x >> 5, lane = threadIdx.x & 31;
    float sg = 0.0f;
    for (int hh = lane; hh < HDIM; hh += 32)
        sg = fmaf(xs[hh], gw[hh * NEXP + w], sg);
#pragma unroll
    for (int o = 16; o; o >>= 1) sg += __shfl_xor_sync(0xffffffffu, sg, o);
    if (lane == 0) lg[w] = sg + gb[w];
    __syncthreads();
    if (threadIdx.x == 0) {
        int i0 = 0;
        for (int e = 1; e < NEXP; e++) if (lg[e] > lg[i0]) i0 = e;
        int i1 = -1;
        for (int e = 0; e < NEXP; e++) {
            if (e == i0) continue;
            if (i1 < 0 || lg[e] > lg[i1]) i1 = e;
        }
        const float e1 = __expf(lg[i1] - lg[i0]);
        const float den = 1.0f / (1.0f + e1);
        g_top_e[2*row]   = i0; g_top_e[2*row+1] = i1;
        g_top_w[2*row]   = den;
        g_top_w[2*row+1] = e1 * den;
        atomicAdd(&g_cnt[i0], 1);
        atomicAdd(&g_cnt[i1], 1);
    }
}

// ---------------- scatter with inline scan (k_scan folded in) ---------------------------
__global__ void __launch_bounds__(256) k_scatter()
{
    int offl[NEXP];
    {
        int s = 0;
#pragma unroll
        for (int e = 0; e < NEXP; e++) { offl[e] = s; s += g_cnt[e]; }
    }
    if (blockIdx.x == 0 && threadIdx.x == 0) {
#pragma unroll
        for (int e = 0; e < NEXP; e++) g_off[e] = offl[e];
    }
    const int t = blockIdx.x * 256 + threadIdx.x;
    if (t >= NTOK) return;
#pragma unroll
    for (int k = 0; k < 2; k++) {
        const int e = g_top_e[2*t + k];
        const int p = atomicAdd(&g_cur[e], 1);
        const int pos = offl[e] + p;
        g_slot_token[pos] = t;
        g_slot_w[pos] = g_top_w[2*t + k];
        g_token_slot[2*t + k] = pos;
    }
}

// ---------------- MoE GEMM1 (tf32 tensor, deep-k) ----------------------------------------
__global__ void __launch_bounds__(256) k_moe1(const float* __restrict__ w1,
                                              const float* __restrict__ b1)
{
    const int e = blockIdx.z;
    const int cnt = g_cnt[e];
    const int r0b = blockIdx.y * 128;
    if (r0b >= cnt) return;
    const int off = g_off[e];

    __shared__ int toks[128];
    G32_DECLS
    const int n0 = blockIdx.x * 128;

    if (tid < 128) {
        const int r = r0b + tid;
        toks[tid] = (r < cnt) ? g_slot_token[off + r] : -1;
    }
    __syncthreads();
    const int tok = toks[alm];
    const bool aval = (tok >= 0);
    const float* aptr = g_h1 + (size_t)(aval ? tok : 0) * HDIM;
    const float* bptr = w1 + (size_t)e * HDIM * FDIM + n0 + bln;

    G32_PROLOGUE(FDIM, aval)
    G32_LOOP(HDIM/32, FDIM, aval)

#pragma unroll
    for (int mt = 0; mt < 2; mt++) {
        const int r0 = r0b + wm*32 + mt*16 + fg;
        const int r1 = r0 + 8;
#pragma unroll
        for (int nt = 0; nt < 8; nt++) {
            const int col = n0 + wn*64 + nt*8 + fc*2;
            float2 bb = *(const float2*)(b1 + (size_t)e * FDIM + col);
            if (r0 < cnt)
                *(float2*)(g_hidden + (size_t)(off + r0) * FDIM + col) =
                    make_float2(fmaxf(acc[mt][nt][0] + bb.x, 0.f),
                                fmaxf(acc[mt][nt][1] + bb.y, 0.f));
            if (r1 < cnt)
                *(float2*)(g_hidden + (size_t)(off + r1) * FDIM + col) =
                    make_float2(fmaxf(acc[mt][nt][2] + bb.x, 0.f),
                                fmaxf(acc[mt][nt][3] + bb.y, 0.f));
        }
    }
}

// ---------------- MoE GEMM2 (tf32 tensor, deep-k) ------------------------------------------
__global__ void __launch_bounds__(256) k_moe2(const float* __restrict__ w2,
                                              const float* __restrict__ b2)
{
    const int e = blockIdx.z;
    const int cnt = g_cnt[e];
    const int r0b = blockIdx.y * 128;
    if (r0b >= cnt) return;
    const int off = g_off[e];

    G32_DECLS
    const int n0 = blockIdx.x * 128;

    const int r = r0b + alm;
    const bool aval = (r < cnt);
    const float* aptr = g_hidden + (size_t)(off + (aval ? r : 0)) * FDIM;
    const float* bptr = w2 + (size_t)e * FDIM * HDIM + n0 + bln;

    G32_PROLOGUE(HDIM, aval)
    G32_LOOP(FDIM/32, HDIM, aval)

#pragma unroll
    for (int mt = 0; mt < 2; mt++) {
        const int r0 = r0b + wm*32 + mt*16 + fg;
        const int r1 = r0 + 8;
#pragma unroll
        for (int nt = 0; nt < 8; nt++) {
            const int col = n0 + wn*64 + nt*8 + fc*2;
            float2 bb = *(const float2*)(b2 + (size_t)e * HDIM + col);
            if (r0 < cnt)
                *(float2*)(g_y + (size_t)(off + r0) * HDIM + col) =
                    make_float2(acc[mt][nt][0] + bb.x, acc[mt][nt][1] + bb.y);
            if (r1 < cnt)
                *(float2*)(g_y + (size_t)(off + r1) * HDIM + col) =
                    make_float2(acc[mt][nt][2] + bb.x, acc[mt][nt][3] + bb.y);
        }
    }
}

// ---------------- combine + LN2 -----------------------------------------------------------
__global__ void __launch_bounds__(256) k_combine(const float* __restrict__ mom_in,
                                                 const float* __restrict__ g,
                                                 const float* __restrict__ b,
                                                 float* __restrict__ out)
{
    __shared__ float sbuf[8];
    const int t = blockIdx.x;
    const int s0 = g_token_slot[2*t], s1 = g_token_slot[2*t + 1];
    const float w0 = g_slot_w[s0], w1 = g_slot_w[s1];
    const int c0 = threadIdx.x * 4;

    float4 h1v = *(const float4*)(g_h1 + (size_t)t * HDIM + c0);
    float4 mv  = *(const float4*)(mom_in + (size_t)t * HDIM + c0);
    float4 y0  = *(const float4*)(g_y + (size_t)s0 * HDIM + c0);
    float4 y1  = *(const float4*)(g_y + (size_t)s1 * HDIM + c0);

    float momn[4], x[4];
    momn[0] = 0.7f*mv.x + w0*y0.x + w1*y1.x;
    momn[1] = 0.7f*mv.y + w0*y0.y + w1*y1.y;
    momn[2] = 0.7f*mv.z + w0*y0.z + w1*y1.z;
    momn[3] = 0.7f*mv.w + w0*y0.w + w1*y1.w;
    x[0] = h1v.x - momn[0]; x[1] = h1v.y - momn[1];
    x[2] = h1v.z - momn[2]; x[3] = h1v.w - momn[3];

    float s  = x[0] + x[1] + x[2] + x[3];
    float s2 = x[0]*x[0] + x[1]*x[1] + x[2]*x[2] + x[3]*x[3];
    s  = blk_sum8(s,  sbuf);
    s2 = blk_sum8(s2, sbuf);
    const float mu = s * (1.0f / HDIM);
    const float var = s2 * (1.0f / HDIM) - mu * mu;
    const float inv = rsqrtf(var + 1e-5f);
    float4 gv = *(const float4*)(g + c0);
    float4 bv = *(const float4*)(b + c0);

    *(float4*)(out + (size_t)t * HDIM + c0) = make_float4(
        (x[0] - mu) * inv * gv.x + bv.x,
        (x[1] - mu) * inv * gv.y + bv.y,
        (x[2] - mu) * inv * gv.z + bv.z,
        (x[3] - mu) * inv * gv.w + bv.w);
    *(float4*)(out + (size_t)NTOK * HDIM + (size_t)t * HDIM + c0) =
        make_float4(momn[0], momn[1], momn[2], momn[3]);
}

// ---------------- launch ---------------------------------------------------------------------
extern "C" void kernel_launch(void* const* d_in, const int* in_sizes, int n_in,
                              void* d_out, int out_size)
{
    const float* h       = (const float*)d_in[0];
    const float* h_cache = (const float*)d_in[1];
    const float* pos     = (const float*)d_in[2];
    const float* mom     = (const float*)d_in[3];
    const float* Wq      = (const float*)d_in[4];
    const float* Wk      = (const float*)d_in[5];
    const float* Wv      = (const float*)d_in[6];
    const float* Wo      = (const float*)d_in[7];
    const float* gate_w  = (const float*)d_in[8];
    const float* gate_b  = (const float*)d_in[9];
    const float* w1      = (const float*)d_in[10];
    const float* b1      = (const float*)d_in[11];
    const float* w2      = (const float*)d_in[12];
    const float* b2      = (const float*)d_in[13];
    const float* ln1g    = (const float*)d_in[14];
    const float* ln1b    = (const float*)d_in[15];
    const float* ln2g    = (const float*)d_in[16];
    const float* ln2b    = (const float*)d_in[17];
    float* out = (float*)d_out;

    cudaFuncSetAttribute(k_qkv,  cudaFuncAttributeMaxDynamicSharedMemorySize, G32_SMEM_BYTES);
    cudaFuncSetAttribute(k_wo,   cudaFuncAttributeMaxDynamicSharedMemorySize, G32_SMEM_BYTES);
    cudaFuncSetAttribute(k_moe1, cudaFuncAttributeMaxDynamicSharedMemorySize, G32_SMEM_BYTES);
    cudaFuncSetAttribute(k_moe2, cudaFuncAttributeMaxDynamicSharedMemorySize, G32_SMEM_BYTES);

    k_init<<<1, 32>>>();
    k_qkv<<<1280, 256, G32_SMEM_BYTES>>>(h, h_cache, Wq, Wk, Wv);
    k_scores<<<dim3(SEQ_L/64, SEQ_M/128, NBH), 256>>>(pos);
    k_softmax<<<NBH*SEQ_M/8, 256>>>();
    k_av<<<dim3(SEQ_M/128, NBH), 256>>>();
    k_wo<<<dim3(HDIM/128, NTOK/128), 256, G32_SMEM_BYTES>>>(Wo, h);
    k_ln1gate<<<NTOK, 256>>>(ln1g, ln1b, gate_w, gate_b);
    k_scatter<<<NTOK/256, 256>>>();
    k_moe1<<<dim3(FDIM/128, NSLOT/128, NEXP), 256, G32_SMEM_BYTES>>>(w1, b1);
    k_moe2<<<dim3(HDIM/128, NSLOT/128, NEXP), 256, G32_SMEM_BYTES>>>(w2, b2);
    k_combine<<<NTOK, 256>>>(mom, ln2g, ln2b, out);
}